// round 14
// baseline (speedup 1.0000x reference)
#include <cuda_runtime.h>
#include <cuda_bf16.h>
#include <cstdint>

// ---------------------------------------------------------------------------
// Problem constants
// ---------------------------------------------------------------------------
#define A_TOT 20000
#define L_TOT 80000
#define N_TOT 100000
#define E_AA  400000
#define E_AL  800000
#define ETOT  (E_AA + 2 * E_AL)
#define HDIM  64
#define BN_EPS 1e-5f
#define AGENT_BLOCKS ((A_TOT + 63) / 64)   // 313
#define LANE_BLOCKS  ((L_TOT + 63) / 64)   // 1250

typedef unsigned long long u64;

// ---------------------------------------------------------------------------
// Scratch (device globals)
// ---------------------------------------------------------------------------
__device__ float g_x[N_TOT * HDIM];
__device__ float g_h[N_TOT * HDIM];
__device__ float g_out1[N_TOT * HDIM];
__device__ float g_deg[N_TOT];
__device__ float g_dinv[N_TOT];
__device__ float g_stats[256];
__device__ int   g_cnt[N_TOT];
__device__ int   g_rowptr[N_TOT + 1];
__device__ int   g_cursor[N_TOT];
__device__ int2  g_epack[ETOT];

// ---------------------------------------------------------------------------
// math helpers
// ---------------------------------------------------------------------------
__device__ __forceinline__ float sigmoidf_(float x) {
    return 1.0f / (1.0f + __expf(-x));
}
__device__ __forceinline__ float tanh_fast(float x) {
    float y;
    asm("tanh.approx.f32 %0, %1;" : "=f"(y) : "f"(x));
    return y;
}
__device__ __forceinline__ float sig_fast(float x) {
    return fmaf(0.5f, tanh_fast(0.5f * x), 0.5f);
}
__device__ __forceinline__ void mma_bf16(float* d, const uint32_t* a,
                                         uint32_t b0, uint32_t b1) {
    asm volatile(
        "mma.sync.aligned.m16n8k16.row.col.f32.bf16.bf16.f32 "
        "{%0,%1,%2,%3}, {%4,%5,%6,%7}, {%8,%9}, {%0,%1,%2,%3};"
        : "+f"(d[0]), "+f"(d[1]), "+f"(d[2]), "+f"(d[3])
        : "r"(a[0]), "r"(a[1]), "r"(a[2]), "r"(a[3]), "r"(b0), "r"(b1));
}
#define LDSM4(r, addr)                                                        \
    asm volatile("ldmatrix.sync.aligned.m8n8.x4.shared.b16 {%0,%1,%2,%3}, [%4];" \
        : "=r"((r)[0]), "=r"((r)[1]), "=r"((r)[2]), "=r"((r)[3]) : "r"(addr))
#define BAR_GRP(id)                                                           \
    asm volatile("bar.sync %0, 256;" :: "r"(id) : "memory")

__device__ __forceinline__ uint32_t smem_u32(const void* p) {
    uint32_t a;
    asm("{ .reg .u64 t; cvta.to.shared.u64 t, %1; cvt.u32.u64 %0, t; }"
        : "=r"(a) : "l"(p));
    return a;
}
__device__ __forceinline__ uint32_t pack_bf2(float a, float b) {
    __nv_bfloat16 ha = __float2bfloat16(a), hb = __float2bfloat16(b);
    return (uint32_t)__bfloat16_as_ushort(ha) |
           ((uint32_t)__bfloat16_as_ushort(hb) << 16);
}
__device__ __forceinline__ float bf_lo(uint32_t v) {
    return __bfloat162float(__ushort_as_bfloat16((unsigned short)(v & 0xFFFF)));
}
__device__ __forceinline__ float bf_hi(uint32_t v) {
    return __bfloat162float(__ushort_as_bfloat16((unsigned short)(v >> 16)));
}

// ---------------------------------------------------------------------------
// LSTM body (device function), identical algorithm to R12's kernel.
//   A [64 rows][592 B]: [h_hi0 | h_lo0 | h_hi1 | h_lo1 | x0(32B) | x1(32B)]
//   B [256 cols][304 B]: [W_hi(64k) | W_lo(64k) | Xblk(16k)]
//   512 thr, 16 warps 2m x 8n; group barrier bar.sync(1+wm,256);
//   ks-major fragment-reuse mainloop; double-buffered h/x, 1 barrier/t.
// ---------------------------------------------------------------------------
#define ASTR 592
#define BSTRB 304
#define SM_B_OFF (64 * ASTR)                        // 37,888
#define LSTM_SMEM (64 * ASTR + 256 * BSTRB)         // 115,712 B

template <int T, int D, bool MEAN>
__device__ __forceinline__ void lstm_body(
    char* smem,
    const float* __restrict__ xin,
    const float* __restrict__ Wih,
    const float* __restrict__ Whh,
    const float* __restrict__ bias,
    float* __restrict__ emb_out,
    int xnode_off, int nrows, int base)
{
    constexpr int TD = T * D;
    uint32_t* Aw = (uint32_t*)smem;
    const uint32_t sb = smem_u32(smem);

    const int tid  = threadIdx.x;
    const int wid  = tid >> 5, lane = tid & 31;
    const int lrow = lane >> 2, q = lane & 3;
    const int wm = wid >> 3, wn = wid & 7;   // 2m x 8n warp grid

    // ---- zero A + B ----
    for (int i = tid; i < 64 * (ASTR / 4) + 256 * (BSTRB / 4); i += 512) Aw[i] = 0;
    __syncthreads();

    // ---- fill B: W_hi (k0-63), W_lo (k64-127) ----
    for (int idx = tid; idx < 256 * 64; idx += 512) {
        int j = idx >> 6, k = idx & 63;
        int g = j >> 6, u = j & 63;
        int n = ((u >> 3) << 5) + (g << 3) + (u & 7);
        float w = Whh[idx];
        __nv_bfloat16 hi = __float2bfloat16(w);
        __nv_bfloat16 lo = __float2bfloat16(w - __bfloat162float(hi));
        char* bp = smem + SM_B_OFF + n * BSTRB;
        *(__nv_bfloat16*)(bp + 2 * k)       = hi;
        *(__nv_bfloat16*)(bp + 128 + 2 * k) = lo;
    }
    // B X block (k128-143): [Wih_hi | Wih_hi | Wih_lo | bias]
    if (tid < 256) {
        int j = tid;
        int g = j >> 6, u = j & 63;
        int n = ((u >> 3) << 5) + (g << 3) + (u & 7);
        char* bp = smem + SM_B_OFF + n * BSTRB + 256;
#pragma unroll
        for (int d = 0; d < D; ++d) {
            float w = Wih[j * D + d];
            __nv_bfloat16 hi = __float2bfloat16(w);
            __nv_bfloat16 lo = __float2bfloat16(w - __bfloat162float(hi));
            *(__nv_bfloat16*)(bp + 2 * d)           = hi;
            *(__nv_bfloat16*)(bp + 2 * (D + d))     = hi;
            *(__nv_bfloat16*)(bp + 2 * (2 * D + d)) = lo;
        }
        *(__nv_bfloat16*)(bp + 2 * (3 * D)) = __float2bfloat16(bias[j]);
    }
    // A: const-1 in both x buffers; x(t=0) into buffer 0
    if (tid < 64) {
        char* ap = smem + tid * ASTR;
        *(__nv_bfloat16*)(ap + 512 + 2 * (3 * D)) = __float2bfloat16(1.0f);
        *(__nv_bfloat16*)(ap + 544 + 2 * (3 * D)) = __float2bfloat16(1.0f);
    }
    if (tid < 192) {
        int r = tid & 63, part = tid >> 6;
        char* ap = smem + r * ASTR + 512;   // buffer 0
        bool ok = (base + r < nrows);
        const float* xr = xin + (size_t)(base + r) * TD;
#pragma unroll
        for (int d = 0; d < D; ++d) {
            float v = ok ? xr[d] : 0.0f;
            __nv_bfloat16 hi = __float2bfloat16(v);
            if (part == 0)      *(__nv_bfloat16*)(ap + 2 * d) = hi;
            else if (part == 1) *(__nv_bfloat16*)(ap + 2 * (D + d)) =
                                    __float2bfloat16(v - __bfloat162float(hi));
            else                *(__nv_bfloat16*)(ap + 2 * (2 * D + d)) = hi;
        }
    }
    __syncthreads();

    const uint32_t aAddr0 = sb + (uint32_t)(wm * 32 + (lane & 15)) * ASTR
                          + (uint32_t)((lane >> 4) * 8) * 2;
    const uint32_t bAddr0 = sb + SM_B_OFF
                          + (uint32_t)(wn * 32 + (lane >> 4) * 8 + (lane & 7)) * BSTRB
                          + (uint32_t)(((lane >> 3) & 1)) * 16;

    const int gl = tid & 255;
    const int xpart = gl >> 5;
    const int xrow  = wm * 32 + (gl & 31);

    float cst[8], outv[8];
#pragma unroll
    for (int i = 0; i < 8; ++i) { cst[i] = 0.0f; outv[i] = 0.0f; }

#pragma unroll 1
    for (int t = 0; t < T; ++t) {
        const uint32_t rb = (uint32_t)(t & 1);
        const uint32_t wbuf = rb ^ 1u;
        const uint32_t hbase = rb * 256u;
        const uint32_t xoff  = 512u + rb * 32u;

        float acc[2][4][4];
#pragma unroll
        for (int mt = 0; mt < 2; ++mt)
#pragma unroll
            for (int nt = 0; nt < 4; ++nt)
#pragma unroll
                for (int i = 0; i < 4; ++i) acc[mt][nt][i] = 0.0f;

        if (t > 0) {
#pragma unroll
            for (int ks = 0; ks < 4; ++ks) {
                const uint32_t ka = hbase + ks * 32;
                const uint32_t kb = ks * 32;
                uint32_t a0[4], a1[4], q0[4], q1[4];
                LDSM4(q0, bAddr0 + kb);
                LDSM4(q1, bAddr0 + 16 * BSTRB + kb);
                LDSM4(a0, aAddr0 + ka);
                LDSM4(a1, aAddr0 + 16 * ASTR + ka);
                mma_bf16(acc[0][0], a0, q0[0], q0[1]);
                mma_bf16(acc[0][1], a0, q0[2], q0[3]);
                mma_bf16(acc[0][2], a0, q1[0], q1[1]);
                mma_bf16(acc[0][3], a0, q1[2], q1[3]);
                mma_bf16(acc[1][0], a1, q0[0], q0[1]);
                mma_bf16(acc[1][1], a1, q0[2], q0[3]);
                mma_bf16(acc[1][2], a1, q1[0], q1[1]);
                mma_bf16(acc[1][3], a1, q1[2], q1[3]);
                LDSM4(a0, aAddr0 + ka + 128);
                LDSM4(a1, aAddr0 + 16 * ASTR + ka + 128);
                mma_bf16(acc[0][0], a0, q0[0], q0[1]);
                mma_bf16(acc[0][1], a0, q0[2], q0[3]);
                mma_bf16(acc[0][2], a0, q1[0], q1[1]);
                mma_bf16(acc[0][3], a0, q1[2], q1[3]);
                mma_bf16(acc[1][0], a1, q0[0], q0[1]);
                mma_bf16(acc[1][1], a1, q0[2], q0[3]);
                mma_bf16(acc[1][2], a1, q1[0], q1[1]);
                mma_bf16(acc[1][3], a1, q1[2], q1[3]);
                LDSM4(q0, bAddr0 + kb + 128);
                LDSM4(q1, bAddr0 + 16 * BSTRB + kb + 128);
                LDSM4(a0, aAddr0 + ka);
                LDSM4(a1, aAddr0 + 16 * ASTR + ka);
                mma_bf16(acc[0][0], a0, q0[0], q0[1]);
                mma_bf16(acc[0][1], a0, q0[2], q0[3]);
                mma_bf16(acc[0][2], a0, q1[0], q1[1]);
                mma_bf16(acc[0][3], a0, q1[2], q1[3]);
                mma_bf16(acc[1][0], a1, q0[0], q0[1]);
                mma_bf16(acc[1][1], a1, q0[2], q0[3]);
                mma_bf16(acc[1][2], a1, q1[0], q1[1]);
                mma_bf16(acc[1][3], a1, q1[2], q1[3]);
            }
        }
        // x pass
        {
            uint32_t a0[4], a1[4], q0[4], q1[4];
            LDSM4(a0, aAddr0 + xoff);
            LDSM4(a1, aAddr0 + 16 * ASTR + xoff);
            LDSM4(q0, bAddr0 + 256);
            LDSM4(q1, bAddr0 + 16 * BSTRB + 256);
            mma_bf16(acc[0][0], a0, q0[0], q0[1]);
            mma_bf16(acc[0][1], a0, q0[2], q0[3]);
            mma_bf16(acc[0][2], a0, q1[0], q1[1]);
            mma_bf16(acc[0][3], a0, q1[2], q1[3]);
            mma_bf16(acc[1][0], a1, q0[0], q0[1]);
            mma_bf16(acc[1][1], a1, q0[2], q0[3]);
            mma_bf16(acc[1][2], a1, q1[0], q1[1]);
            mma_bf16(acc[1][3], a1, q1[2], q1[3]);
        }

        // epilogue -> writes h(t+1) into other buffer
#pragma unroll
        for (int mt = 0; mt < 2; ++mt)
#pragma unroll
            for (int half = 0; half < 2; ++half) {
                float hpair[2];
#pragma unroll
                for (int jp = 0; jp < 2; ++jp) {
                    int rg = half * 2 + jp;
                    float gi = acc[mt][0][rg];
                    float gf = acc[mt][1][rg];
                    float gg = acc[mt][2][rg];
                    float go = acc[mt][3][rg];
                    int ci = mt * 4 + half * 2 + jp;
                    float cn = fmaf(sig_fast(gf), cst[ci],
                                    sig_fast(gi) * tanh_fast(gg));
                    cst[ci] = cn;
                    float h = sig_fast(go) * tanh_fast(cn);
                    if (MEAN) outv[ci] += h;
                    hpair[jp] = h;
                }
                __nv_bfloat16 h0 = __float2bfloat16(hpair[0]);
                __nv_bfloat16 h1 = __float2bfloat16(hpair[1]);
                uint32_t hi2 = (uint32_t)__bfloat16_as_ushort(h0) |
                               ((uint32_t)__bfloat16_as_ushort(h1) << 16);
                uint32_t lo2 = pack_bf2(hpair[0] - __bfloat162float(h0),
                                        hpair[1] - __bfloat162float(h1));
                int row = wm * 32 + mt * 16 + half * 8 + lrow;
                int uw  = wn * 4 + q;
                Aw[row * (ASTR / 4) + wbuf * 64 + uw]      = hi2;
                Aw[row * (ASTR / 4) + wbuf * 64 + 32 + uw] = lo2;
            }

        // fill x(t+1) into other x buffer (own wm rows only)
        if (t + 1 < T && xpart < 3) {
            char* ap = smem + xrow * ASTR + 512 + wbuf * 32;
            bool ok = (base + xrow < nrows);
            const float* xr = xin + (size_t)(base + xrow) * TD + (t + 1) * D;
#pragma unroll
            for (int d = 0; d < D; ++d) {
                float v = ok ? xr[d] : 0.0f;
                __nv_bfloat16 hi = __float2bfloat16(v);
                if (xpart == 0)      *(__nv_bfloat16*)(ap + 2 * d) = hi;
                else if (xpart == 1) *(__nv_bfloat16*)(ap + 2 * (D + d)) =
                                         __float2bfloat16(v - __bfloat162float(hi));
                else                 *(__nv_bfloat16*)(ap + 2 * (2 * D + d)) = hi;
            }
        }
        BAR_GRP(1 + wm);
    }

    // outputs (final h lives in buffer T&1)
    const float scale = MEAN ? (1.0f / T) : 1.0f;
    const uint32_t fb = (uint32_t)(T & 1);
#pragma unroll
    for (int mt = 0; mt < 2; ++mt)
#pragma unroll
        for (int half = 0; half < 2; ++half) {
            int row = wm * 32 + mt * 16 + half * 8 + lrow;
            int grow = base + row;
            if (grow >= nrows) continue;
            int unit0 = wn * 8 + 2 * q;
            float2 v;
            if (MEAN) {
                int ci0 = mt * 4 + half * 2;
                v = make_float2(outv[ci0] * scale, outv[ci0 + 1] * scale);
            } else {
                uint32_t hi2 = Aw[row * (ASTR / 4) + fb * 64 + wn * 4 + q];
                uint32_t lo2 = Aw[row * (ASTR / 4) + fb * 64 + 32 + wn * 4 + q];
                v = make_float2(bf_lo(hi2) + bf_lo(lo2), bf_hi(hi2) + bf_hi(lo2));
            }
            *(float2*)&emb_out[(size_t)grow * 64 + unit0] = v;
            *(float2*)&g_x[(size_t)(xnode_off + grow) * 64 + unit0] = v;
        }
}

// Unified launch: agent blocks [0, AGENT_BLOCKS) then lane blocks.
__global__ __launch_bounds__(512, 2)
void lstm_unified_kernel(const float* __restrict__ agent_hist,
                         const float* __restrict__ Wih_a,
                         const float* __restrict__ Whh_a,
                         const float* __restrict__ b_a,
                         const float* __restrict__ lane_nodes,
                         const float* __restrict__ Wih_l,
                         const float* __restrict__ Whh_l,
                         const float* __restrict__ b_l,
                         float* __restrict__ out)
{
    extern __shared__ char smem[];
    if (blockIdx.x < AGENT_BLOCKS) {
        lstm_body<20, 5, false>(smem, agent_hist, Wih_a, Whh_a, b_a,
                                out, 0, A_TOT, blockIdx.x * 64);
    } else {
        lstm_body<10, 2, true>(smem, lane_nodes, Wih_l, Whh_l, b_l,
                               out + (size_t)2 * A_TOT * 64, A_TOT, L_TOT,
                               (blockIdx.x - AGENT_BLOCKS) * 64);
    }
}

// ---------------------------------------------------------------------------
// edge decode + CSR build
// ---------------------------------------------------------------------------
__device__ __forceinline__ void edge_decode(
    int e,
    const int* __restrict__ aa_src, const int* __restrict__ aa_dst,
    const float* __restrict__ len_aa,
    const int* __restrict__ al_a, const int* __restrict__ al_l,
    const float* __restrict__ len_al,
    int& src, int& dst, float& len)
{
    if (e < E_AA) {
        src = aa_src[e]; dst = aa_dst[e]; len = len_aa[e];
    } else if (e < E_AA + E_AL) {
        int i = e - E_AA;
        src = al_a[i]; dst = A_TOT + al_l[i]; len = len_al[i];
    } else {
        int i = e - E_AA - E_AL;
        src = A_TOT + al_l[i]; dst = al_a[i]; len = len_al[i];
    }
}

__global__ void init_kernel() {
    int i = blockIdx.x * blockDim.x + threadIdx.x;
    if (i < N_TOT) { g_deg[i] = 1.0f; g_cnt[i] = 0; }
    if (i < 256) g_stats[i] = 0.0f;
}

__global__ void hist_kernel(const int* __restrict__ aa_src, const int* __restrict__ aa_dst,
                            const float* __restrict__ len_aa,
                            const int* __restrict__ al_a, const int* __restrict__ al_l,
                            const float* __restrict__ len_al,
                            const float* __restrict__ w_e, const float* __restrict__ b_e) {
    int e = blockIdx.x * blockDim.x + threadIdx.x;
    if (e >= ETOT) return;
    int src, dst; float len;
    edge_decode(e, aa_src, aa_dst, len_aa, al_a, al_l, len_al, src, dst, len);
    float w = sigmoidf_(fmaf(len, w_e[0], b_e[0]));
    atomicAdd(&g_deg[dst], w);
    atomicAdd(&g_cnt[dst], 1);
}

// scan + dinv fused (dinv computed during the rowptr sweep)
__global__ __launch_bounds__(1024)
void scan_kernel() {
    __shared__ int ssum[1024];
    const int C = (N_TOT + 1023) / 1024;
    int t = threadIdx.x;
    int beg = t * C, end = min(beg + C, N_TOT);
    int s = 0;
    for (int i = beg; i < end; ++i) s += g_cnt[i];
    ssum[t] = s;
    __syncthreads();
    for (int off = 1; off < 1024; off <<= 1) {
        int v = (t >= off) ? ssum[t - off] : 0;
        __syncthreads();
        ssum[t] += v;
        __syncthreads();
    }
    int run = ssum[t] - s;
    for (int i = beg; i < end; ++i) {
        g_rowptr[i] = run;
        g_cursor[i] = run;
        run += g_cnt[i];
        float d = g_deg[i];
        g_dinv[i] = (d > 0.0f) ? rsqrtf(d) : 0.0f;
    }
    if (t == 1023) g_rowptr[N_TOT] = ETOT;
}

__global__ void scatter_kernel(const int* __restrict__ aa_src, const int* __restrict__ aa_dst,
                               const float* __restrict__ len_aa,
                               const int* __restrict__ al_a, const int* __restrict__ al_l,
                               const float* __restrict__ len_al,
                               const float* __restrict__ w_e, const float* __restrict__ b_e) {
    int e = blockIdx.x * blockDim.x + threadIdx.x;
    if (e >= ETOT) return;
    int src, dst; float len;
    edge_decode(e, aa_src, aa_dst, len_aa, al_a, al_l, len_al, src, dst, len);
    float w = sigmoidf_(fmaf(len, w_e[0], b_e[0]));
    float nrm = g_dinv[src] * w * g_dinv[dst];
    int pos = atomicAdd(&g_cursor[dst], 1);
    g_epack[pos] = make_int2(src, __float_as_int(nrm));
}

// ---------------------------------------------------------------------------
__global__ __launch_bounds__(256)
void lin_kernel(const float* __restrict__ W, int in_sel, int use_bn) {
    __shared__ float Ws[64 * 65];
    __shared__ float xsh[64 * 65];
    const float* in = in_sel ? g_out1 : g_x;

    int tid = threadIdx.x;
    for (int idx = tid; idx < 64 * 64; idx += 256) {
        int k = idx >> 6, j = idx & 63;
        Ws[k * 65 + j] = W[idx];
    }
    int base = blockIdx.x * 64;
    for (int idx = tid; idx < 64 * 64; idx += 256) {
        int r = idx >> 6, k = idx & 63;
        int row = base + r;
        float v = (row < N_TOT) ? in[(size_t)row * 64 + k] : 0.0f;
        if (use_bn) v = fmaxf(fmaf(v, g_stats[128 + k], g_stats[192 + k]), 0.0f);
        xsh[r * 65 + k] = v;
    }
    __syncthreads();

    int j = tid & 63, rl = tid >> 6;
    for (int rr = rl; rr < 64; rr += 4) {
        float a = 0.0f;
#pragma unroll
        for (int k = 0; k < 64; ++k) a = fmaf(xsh[rr * 65 + k], Ws[k * 65 + j], a);
        int row = base + rr;
        if (row < N_TOT) g_h[(size_t)row * 64 + j] = a;
    }
}

// ---------------------------------------------------------------------------
// CSR aggregation, unroll-4 for MLP
// ---------------------------------------------------------------------------
__global__ __launch_bounds__(256)
void agg_csr_kernel(const float* __restrict__ bvec, float* __restrict__ dout, int map) {
    int node = blockIdx.x * 8 + (threadIdx.x >> 5);
    if (node >= N_TOT) return;
    int lane = threadIdx.x & 31;

    int beg = g_rowptr[node], end = g_rowptr[node + 1];

    float ax = 0.0f, ay = 0.0f;
    int e = beg;
    for (; e + 3 < end; e += 4) {
        int2 p0 = g_epack[e];
        int2 p1 = g_epack[e + 1];
        int2 p2 = g_epack[e + 2];
        int2 p3 = g_epack[e + 3];
        float2 v0 = *(const float2*)&g_h[(size_t)p0.x * 64 + 2 * lane];
        float2 v1 = *(const float2*)&g_h[(size_t)p1.x * 64 + 2 * lane];
        float2 v2 = *(const float2*)&g_h[(size_t)p2.x * 64 + 2 * lane];
        float2 v3 = *(const float2*)&g_h[(size_t)p3.x * 64 + 2 * lane];
        float n0 = __int_as_float(p0.y), n1 = __int_as_float(p1.y);
        float n2 = __int_as_float(p2.y), n3 = __int_as_float(p3.y);
        ax = fmaf(v0.x, n0, ax); ay = fmaf(v0.y, n0, ay);
        ax = fmaf(v1.x, n1, ax); ay = fmaf(v1.y, n1, ay);
        ax = fmaf(v2.x, n2, ax); ay = fmaf(v2.y, n2, ay);
        ax = fmaf(v3.x, n3, ax); ay = fmaf(v3.y, n3, ay);
    }
    for (; e < end; ++e) {
        int2 p0 = g_epack[e];
        float2 v0 = *(const float2*)&g_h[(size_t)p0.x * 64 + 2 * lane];
        float n0 = __int_as_float(p0.y);
        ax = fmaf(v0.x, n0, ax); ay = fmaf(v0.y, n0, ay);
    }

    float di = g_dinv[node];
    float dd = di * di;
    float2 hv = *(const float2*)&g_h[(size_t)node * 64 + 2 * lane];
    float2 bv = *(const float2*)&bvec[2 * lane];
    float2 res;
    res.x = fmaf(hv.x, dd, ax) + bv.x;
    res.y = fmaf(hv.y, dd, ay) + bv.y;

    float* op;
    if (map) {
        size_t off = (node < A_TOT) ? ((size_t)(A_TOT + node) * 64)
                                    : ((size_t)(A_TOT + L_TOT + node) * 64);
        op = dout + off;
    } else {
        op = g_out1 + (size_t)node * 64;
    }
    *(float2*)(op + 2 * lane) = res;
}

// ---------------------------------------------------------------------------
__global__ __launch_bounds__(256)
void bn_stats_kernel() {
    __shared__ float sh[512];
    int tid = threadIdx.x;
    int j = tid & 63;
    float s = 0.0f, s2 = 0.0f;
    for (int row = blockIdx.x * 4 + (tid >> 6); row < N_TOT; row += gridDim.x * 4) {
        float v = g_out1[(size_t)row * 64 + j];
        s += v; s2 += v * v;
    }
    sh[tid] = s; sh[256 + tid] = s2;
    __syncthreads();
    if (tid < 64) {
        float t = sh[tid] + sh[tid + 64] + sh[tid + 128] + sh[tid + 192];
        atomicAdd(&g_stats[tid], t);
    } else if (tid < 128) {
        int jj = tid - 64;
        float t = sh[256 + jj] + sh[256 + jj + 64] + sh[256 + jj + 128] + sh[256 + jj + 192];
        atomicAdd(&g_stats[64 + jj], t);
    }
}

__global__ void bn_final_kernel(const float* __restrict__ gamma, const float* __restrict__ beta) {
    int j = threadIdx.x;
    if (j >= 64) return;
    float mean = g_stats[j] * (1.0f / N_TOT);
    float var  = g_stats[64 + j] * (1.0f / N_TOT) - mean * mean;
    float rs   = rsqrtf(var + BN_EPS);
    float sc   = rs * gamma[j];
    g_stats[128 + j] = sc;
    g_stats[192 + j] = beta[j] - mean * sc;
}

// ---------------------------------------------------------------------------
extern "C" void kernel_launch(void* const* d_in, const int* in_sizes, int n_in,
                              void* d_out, int out_size) {
    const float* agent_hist = (const float*)d_in[0];
    const float* lane_nodes = (const float*)d_in[1];
    const int*   eaa        = (const int*)d_in[2];
    const float* len_aa     = (const float*)d_in[3];
    const int*   eal        = (const int*)d_in[4];
    const float* len_al     = (const float*)d_in[5];
    const float* Wih_a      = (const float*)d_in[6];
    const float* Whh_a      = (const float*)d_in[7];
    const float* b_a        = (const float*)d_in[8];
    const float* Wih_l      = (const float*)d_in[9];
    const float* Whh_l      = (const float*)d_in[10];
    const float* b_l        = (const float*)d_in[11];
    const float* w_e        = (const float*)d_in[12];
    const float* b_e        = (const float*)d_in[13];
    const float* W1         = (const float*)d_in[14];
    const float* b1         = (const float*)d_in[15];
    const float* gamma1     = (const float*)d_in[16];
    const float* beta1      = (const float*)d_in[17];
    const float* W2         = (const float*)d_in[18];
    const float* b2         = (const float*)d_in[19];
    float* out = (float*)d_out;

    const int* aa_src = eaa;
    const int* aa_dst = eaa + E_AA;
    const int* al_a   = eal;
    const int* al_l   = eal + E_AL;

    cudaFuncSetAttribute((const void*)lstm_unified_kernel,
                         cudaFuncAttributeMaxDynamicSharedMemorySize, LSTM_SMEM);

    // launch order: unified LSTM at index 3 (ncu target)
    init_kernel<<<(N_TOT + 255) / 256, 256>>>();
    hist_kernel<<<(ETOT + 255) / 256, 256>>>(aa_src, aa_dst, len_aa, al_a, al_l, len_al, w_e, b_e);
    scan_kernel<<<1, 1024>>>();   // also computes dinv

    lstm_unified_kernel<<<AGENT_BLOCKS + LANE_BLOCKS, 512, LSTM_SMEM>>>(
        agent_hist, Wih_a, Whh_a, b_a, lane_nodes, Wih_l, Whh_l, b_l, out);

    scatter_kernel<<<(ETOT + 255) / 256, 256>>>(aa_src, aa_dst, len_aa, al_a, al_l, len_al, w_e, b_e);

    // conv1
    lin_kernel<<<(N_TOT + 63) / 64, 256>>>(W1, 0, 0);
    agg_csr_kernel<<<(N_TOT + 7) / 8, 256>>>(b1, out, 0);

    // BN
    bn_stats_kernel<<<512, 256>>>();
    bn_final_kernel<<<1, 64>>>(gamma1, beta1);

    // conv2
    lin_kernel<<<(N_TOT + 63) / 64, 256>>>(W2, 1, 1);
    agg_csr_kernel<<<(N_TOT + 7) / 8, 256>>>(b2, out, 1);
}

// round 15
// speedup vs baseline: 1.1308x; 1.1308x over previous
#include <cuda_runtime.h>
#include <cuda_bf16.h>
#include <cstdint>

// ---------------------------------------------------------------------------
// Problem constants
// ---------------------------------------------------------------------------
#define A_TOT 20000
#define L_TOT 80000
#define N_TOT 100000
#define E_AA  400000
#define E_AL  800000
#define ETOT  (E_AA + 2 * E_AL)
#define HDIM  64
#define BN_EPS 1e-5f
#define AGENT_BLOCKS ((A_TOT + 63) / 64)   // 313
#define LANE_BLOCKS  ((L_TOT + 63) / 64)   // 1250

typedef unsigned long long u64;

// ---------------------------------------------------------------------------
// Scratch (device globals)
// ---------------------------------------------------------------------------
__device__ float g_x[N_TOT * HDIM];
__device__ float g_h[N_TOT * HDIM];
__device__ float g_out1[N_TOT * HDIM];
__device__ float g_deg[N_TOT];
__device__ float g_dinv[N_TOT];
__device__ float g_stats[256];
__device__ int   g_cnt[N_TOT];
__device__ int   g_rowptr[N_TOT + 1];
__device__ int   g_cursor[N_TOT];
__device__ int2  g_epack[ETOT];

// ---------------------------------------------------------------------------
// math helpers
// ---------------------------------------------------------------------------
__device__ __forceinline__ float sigmoidf_(float x) {
    return 1.0f / (1.0f + __expf(-x));
}
__device__ __forceinline__ float tanh_fast(float x) {
    float y;
    asm("tanh.approx.f32 %0, %1;" : "=f"(y) : "f"(x));
    return y;
}
__device__ __forceinline__ float sig_fast(float x) {
    return fmaf(0.5f, tanh_fast(0.5f * x), 0.5f);
}
__device__ __forceinline__ void mma_bf16(float* d, const uint32_t* a,
                                         uint32_t b0, uint32_t b1) {
    asm volatile(
        "mma.sync.aligned.m16n8k16.row.col.f32.bf16.bf16.f32 "
        "{%0,%1,%2,%3}, {%4,%5,%6,%7}, {%8,%9}, {%0,%1,%2,%3};"
        : "+f"(d[0]), "+f"(d[1]), "+f"(d[2]), "+f"(d[3])
        : "r"(a[0]), "r"(a[1]), "r"(a[2]), "r"(a[3]), "r"(b0), "r"(b1));
}
#define LDSM4(r, addr)                                                        \
    asm volatile("ldmatrix.sync.aligned.m8n8.x4.shared.b16 {%0,%1,%2,%3}, [%4];" \
        : "=r"((r)[0]), "=r"((r)[1]), "=r"((r)[2]), "=r"((r)[3]) : "r"(addr))
#define BAR_GRP(id)                                                           \
    asm volatile("bar.sync %0, 256;" :: "r"(id) : "memory")

__device__ __forceinline__ uint32_t smem_u32(const void* p) {
    uint32_t a;
    asm("{ .reg .u64 t; cvta.to.shared.u64 t, %1; cvt.u32.u64 %0, t; }"
        : "=r"(a) : "l"(p));
    return a;
}
__device__ __forceinline__ uint32_t pack_bf2(float a, float b) {
    __nv_bfloat16 ha = __float2bfloat16(a), hb = __float2bfloat16(b);
    return (uint32_t)__bfloat16_as_ushort(ha) |
           ((uint32_t)__bfloat16_as_ushort(hb) << 16);
}
__device__ __forceinline__ float bf_lo(uint32_t v) {
    return __bfloat162float(__ushort_as_bfloat16((unsigned short)(v & 0xFFFF)));
}
__device__ __forceinline__ float bf_hi(uint32_t v) {
    return __bfloat162float(__ushort_as_bfloat16((unsigned short)(v >> 16)));
}

// ---------------------------------------------------------------------------
// LSTM body (device function) — same algorithm as the 854us kernel.
// ---------------------------------------------------------------------------
#define ASTR 592
#define BSTRB 304
#define SM_B_OFF (64 * ASTR)                        // 37,888
#define LSTM_SMEM (64 * ASTR + 256 * BSTRB)         // 115,712 B

template <int T, int D, bool MEAN>
__device__ __forceinline__ void lstm_body(
    char* smem,
    const float* __restrict__ xin,
    const float* __restrict__ Wih,
    const float* __restrict__ Whh,
    const float* __restrict__ bias,
    float* __restrict__ emb_out,
    int xnode_off, int nrows, int base)
{
    constexpr int TD = T * D;
    uint32_t* Aw = (uint32_t*)smem;
    const uint32_t sb = smem_u32(smem);

    const int tid  = threadIdx.x;
    const int wid  = tid >> 5, lane = tid & 31;
    const int lrow = lane >> 2, q = lane & 3;
    const int wm = wid >> 3, wn = wid & 7;   // 2m x 8n warp grid

    // ---- zero A + B ----
    for (int i = tid; i < 64 * (ASTR / 4) + 256 * (BSTRB / 4); i += 512) Aw[i] = 0;
    __syncthreads();

    // ---- fill B: W_hi (k0-63), W_lo (k64-127) ----
    for (int idx = tid; idx < 256 * 64; idx += 512) {
        int j = idx >> 6, k = idx & 63;
        int g = j >> 6, u = j & 63;
        int n = ((u >> 3) << 5) + (g << 3) + (u & 7);
        float w = Whh[idx];
        __nv_bfloat16 hi = __float2bfloat16(w);
        __nv_bfloat16 lo = __float2bfloat16(w - __bfloat162float(hi));
        char* bp = smem + SM_B_OFF + n * BSTRB;
        *(__nv_bfloat16*)(bp + 2 * k)       = hi;
        *(__nv_bfloat16*)(bp + 128 + 2 * k) = lo;
    }
    // B X block (k128-143): [Wih_hi | Wih_hi | Wih_lo | bias]
    if (tid < 256) {
        int j = tid;
        int g = j >> 6, u = j & 63;
        int n = ((u >> 3) << 5) + (g << 3) + (u & 7);
        char* bp = smem + SM_B_OFF + n * BSTRB + 256;
#pragma unroll
        for (int d = 0; d < D; ++d) {
            float w = Wih[j * D + d];
            __nv_bfloat16 hi = __float2bfloat16(w);
            __nv_bfloat16 lo = __float2bfloat16(w - __bfloat162float(hi));
            *(__nv_bfloat16*)(bp + 2 * d)           = hi;
            *(__nv_bfloat16*)(bp + 2 * (D + d))     = hi;
            *(__nv_bfloat16*)(bp + 2 * (2 * D + d)) = lo;
        }
        *(__nv_bfloat16*)(bp + 2 * (3 * D)) = __float2bfloat16(bias[j]);
    }
    // A: const-1 in both x buffers; x(t=0) into buffer 0
    if (tid < 64) {
        char* ap = smem + tid * ASTR;
        *(__nv_bfloat16*)(ap + 512 + 2 * (3 * D)) = __float2bfloat16(1.0f);
        *(__nv_bfloat16*)(ap + 544 + 2 * (3 * D)) = __float2bfloat16(1.0f);
    }
    if (tid < 192) {
        int r = tid & 63, part = tid >> 6;
        char* ap = smem + r * ASTR + 512;   // buffer 0
        bool ok = (base + r < nrows);
        const float* xr = xin + (size_t)(base + r) * TD;
#pragma unroll
        for (int d = 0; d < D; ++d) {
            float v = ok ? xr[d] : 0.0f;
            __nv_bfloat16 hi = __float2bfloat16(v);
            if (part == 0)      *(__nv_bfloat16*)(ap + 2 * d) = hi;
            else if (part == 1) *(__nv_bfloat16*)(ap + 2 * (D + d)) =
                                    __float2bfloat16(v - __bfloat162float(hi));
            else                *(__nv_bfloat16*)(ap + 2 * (2 * D + d)) = hi;
        }
    }
    __syncthreads();

    const uint32_t aAddr0 = sb + (uint32_t)(wm * 32 + (lane & 15)) * ASTR
                          + (uint32_t)((lane >> 4) * 8) * 2;
    const uint32_t bAddr0 = sb + SM_B_OFF
                          + (uint32_t)(wn * 32 + (lane >> 4) * 8 + (lane & 7)) * BSTRB
                          + (uint32_t)(((lane >> 3) & 1)) * 16;

    const int gl = tid & 255;
    const int xpart = gl >> 5;
    const int xrow  = wm * 32 + (gl & 31);

    float cst[8], outv[8];
#pragma unroll
    for (int i = 0; i < 8; ++i) { cst[i] = 0.0f; outv[i] = 0.0f; }

#pragma unroll 1
    for (int t = 0; t < T; ++t) {
        const uint32_t rb = (uint32_t)(t & 1);
        const uint32_t wbuf = rb ^ 1u;
        const uint32_t hbase = rb * 256u;
        const uint32_t xoff  = 512u + rb * 32u;

        float acc[2][4][4];
#pragma unroll
        for (int mt = 0; mt < 2; ++mt)
#pragma unroll
            for (int nt = 0; nt < 4; ++nt)
#pragma unroll
                for (int i = 0; i < 4; ++i) acc[mt][nt][i] = 0.0f;

        if (t > 0) {
#pragma unroll
            for (int ks = 0; ks < 4; ++ks) {
                const uint32_t ka = hbase + ks * 32;
                const uint32_t kb = ks * 32;
                uint32_t a0[4], a1[4], q0[4], q1[4];
                LDSM4(q0, bAddr0 + kb);
                LDSM4(q1, bAddr0 + 16 * BSTRB + kb);
                LDSM4(a0, aAddr0 + ka);
                LDSM4(a1, aAddr0 + 16 * ASTR + ka);
                mma_bf16(acc[0][0], a0, q0[0], q0[1]);
                mma_bf16(acc[0][1], a0, q0[2], q0[3]);
                mma_bf16(acc[0][2], a0, q1[0], q1[1]);
                mma_bf16(acc[0][3], a0, q1[2], q1[3]);
                mma_bf16(acc[1][0], a1, q0[0], q0[1]);
                mma_bf16(acc[1][1], a1, q0[2], q0[3]);
                mma_bf16(acc[1][2], a1, q1[0], q1[1]);
                mma_bf16(acc[1][3], a1, q1[2], q1[3]);
                LDSM4(a0, aAddr0 + ka + 128);
                LDSM4(a1, aAddr0 + 16 * ASTR + ka + 128);
                mma_bf16(acc[0][0], a0, q0[0], q0[1]);
                mma_bf16(acc[0][1], a0, q0[2], q0[3]);
                mma_bf16(acc[0][2], a0, q1[0], q1[1]);
                mma_bf16(acc[0][3], a0, q1[2], q1[3]);
                mma_bf16(acc[1][0], a1, q0[0], q0[1]);
                mma_bf16(acc[1][1], a1, q0[2], q0[3]);
                mma_bf16(acc[1][2], a1, q1[0], q1[1]);
                mma_bf16(acc[1][3], a1, q1[2], q1[3]);
                LDSM4(q0, bAddr0 + kb + 128);
                LDSM4(q1, bAddr0 + 16 * BSTRB + kb + 128);
                LDSM4(a0, aAddr0 + ka);
                LDSM4(a1, aAddr0 + 16 * ASTR + ka);
                mma_bf16(acc[0][0], a0, q0[0], q0[1]);
                mma_bf16(acc[0][1], a0, q0[2], q0[3]);
                mma_bf16(acc[0][2], a0, q1[0], q1[1]);
                mma_bf16(acc[0][3], a0, q1[2], q1[3]);
                mma_bf16(acc[1][0], a1, q0[0], q0[1]);
                mma_bf16(acc[1][1], a1, q0[2], q0[3]);
                mma_bf16(acc[1][2], a1, q1[0], q1[1]);
                mma_bf16(acc[1][3], a1, q1[2], q1[3]);
            }
        }
        // x pass
        {
            uint32_t a0[4], a1[4], q0[4], q1[4];
            LDSM4(a0, aAddr0 + xoff);
            LDSM4(a1, aAddr0 + 16 * ASTR + xoff);
            LDSM4(q0, bAddr0 + 256);
            LDSM4(q1, bAddr0 + 16 * BSTRB + 256);
            mma_bf16(acc[0][0], a0, q0[0], q0[1]);
            mma_bf16(acc[0][1], a0, q0[2], q0[3]);
            mma_bf16(acc[0][2], a0, q1[0], q1[1]);
            mma_bf16(acc[0][3], a0, q1[2], q1[3]);
            mma_bf16(acc[1][0], a1, q0[0], q0[1]);
            mma_bf16(acc[1][1], a1, q0[2], q0[3]);
            mma_bf16(acc[1][2], a1, q1[0], q1[1]);
            mma_bf16(acc[1][3], a1, q1[2], q1[3]);
        }

        // epilogue -> writes h(t+1) into other buffer
#pragma unroll
        for (int mt = 0; mt < 2; ++mt)
#pragma unroll
            for (int half = 0; half < 2; ++half) {
                float hpair[2];
#pragma unroll
                for (int jp = 0; jp < 2; ++jp) {
                    int rg = half * 2 + jp;
                    float gi = acc[mt][0][rg];
                    float gf = acc[mt][1][rg];
                    float gg = acc[mt][2][rg];
                    float go = acc[mt][3][rg];
                    int ci = mt * 4 + half * 2 + jp;
                    float cn = fmaf(sig_fast(gf), cst[ci],
                                    sig_fast(gi) * tanh_fast(gg));
                    cst[ci] = cn;
                    float h = sig_fast(go) * tanh_fast(cn);
                    if (MEAN) outv[ci] += h;
                    hpair[jp] = h;
                }
                __nv_bfloat16 h0 = __float2bfloat16(hpair[0]);
                __nv_bfloat16 h1 = __float2bfloat16(hpair[1]);
                uint32_t hi2 = (uint32_t)__bfloat16_as_ushort(h0) |
                               ((uint32_t)__bfloat16_as_ushort(h1) << 16);
                uint32_t lo2 = pack_bf2(hpair[0] - __bfloat162float(h0),
                                        hpair[1] - __bfloat162float(h1));
                int row = wm * 32 + mt * 16 + half * 8 + lrow;
                int uw  = wn * 4 + q;
                Aw[row * (ASTR / 4) + wbuf * 64 + uw]      = hi2;
                Aw[row * (ASTR / 4) + wbuf * 64 + 32 + uw] = lo2;
            }

        // fill x(t+1) into other x buffer (own wm rows only)
        if (t + 1 < T && xpart < 3) {
            char* ap = smem + xrow * ASTR + 512 + wbuf * 32;
            bool ok = (base + xrow < nrows);
            const float* xr = xin + (size_t)(base + xrow) * TD + (t + 1) * D;
#pragma unroll
            for (int d = 0; d < D; ++d) {
                float v = ok ? xr[d] : 0.0f;
                __nv_bfloat16 hi = __float2bfloat16(v);
                if (xpart == 0)      *(__nv_bfloat16*)(ap + 2 * d) = hi;
                else if (xpart == 1) *(__nv_bfloat16*)(ap + 2 * (D + d)) =
                                         __float2bfloat16(v - __bfloat162float(hi));
                else                 *(__nv_bfloat16*)(ap + 2 * (2 * D + d)) = hi;
            }
        }
        BAR_GRP(1 + wm);
    }

    // outputs (final h lives in buffer T&1)
    const float scale = MEAN ? (1.0f / T) : 1.0f;
    const uint32_t fb = (uint32_t)(T & 1);
#pragma unroll
    for (int mt = 0; mt < 2; ++mt)
#pragma unroll
        for (int half = 0; half < 2; ++half) {
            int row = wm * 32 + mt * 16 + half * 8 + lrow;
            int grow = base + row;
            if (grow >= nrows) continue;
            int unit0 = wn * 8 + 2 * q;
            float2 v;
            if (MEAN) {
                int ci0 = mt * 4 + half * 2;
                v = make_float2(outv[ci0] * scale, outv[ci0 + 1] * scale);
            } else {
                uint32_t hi2 = Aw[row * (ASTR / 4) + fb * 64 + wn * 4 + q];
                uint32_t lo2 = Aw[row * (ASTR / 4) + fb * 64 + 32 + wn * 4 + q];
                v = make_float2(bf_lo(hi2) + bf_lo(lo2), bf_hi(hi2) + bf_hi(lo2));
            }
            *(float2*)&emb_out[(size_t)grow * 64 + unit0] = v;
            *(float2*)&g_x[(size_t)(xnode_off + grow) * 64 + unit0] = v;
        }
}

// Unified launch: agent blocks [0, AGENT_BLOCKS) then lane blocks.
__global__ __launch_bounds__(512, 2)
void lstm_unified_kernel(const float* __restrict__ agent_hist,
                         const float* __restrict__ Wih_a,
                         const float* __restrict__ Whh_a,
                         const float* __restrict__ b_a,
                         const float* __restrict__ lane_nodes,
                         const float* __restrict__ Wih_l,
                         const float* __restrict__ Whh_l,
                         const float* __restrict__ b_l,
                         float* __restrict__ out)
{
    extern __shared__ char smem[];
    if (blockIdx.x < AGENT_BLOCKS) {
        lstm_body<20, 5, false>(smem, agent_hist, Wih_a, Whh_a, b_a,
                                out, 0, A_TOT, blockIdx.x * 64);
    } else {
        lstm_body<10, 2, true>(smem, lane_nodes, Wih_l, Whh_l, b_l,
                               out + (size_t)2 * A_TOT * 64, A_TOT, L_TOT,
                               (blockIdx.x - AGENT_BLOCKS) * 64);
    }
}

// ---------------------------------------------------------------------------
// edge decode + CSR build
// ---------------------------------------------------------------------------
__device__ __forceinline__ void edge_decode(
    int e,
    const int* __restrict__ aa_src, const int* __restrict__ aa_dst,
    const float* __restrict__ len_aa,
    const int* __restrict__ al_a, const int* __restrict__ al_l,
    const float* __restrict__ len_al,
    int& src, int& dst, float& len)
{
    if (e < E_AA) {
        src = aa_src[e]; dst = aa_dst[e]; len = len_aa[e];
    } else if (e < E_AA + E_AL) {
        int i = e - E_AA;
        src = al_a[i]; dst = A_TOT + al_l[i]; len = len_al[i];
    } else {
        int i = e - E_AA - E_AL;
        src = A_TOT + al_l[i]; dst = al_a[i]; len = len_al[i];
    }
}

__global__ void init_kernel() {
    int i = blockIdx.x * blockDim.x + threadIdx.x;
    if (i < N_TOT) { g_deg[i] = 1.0f; g_cnt[i] = 0; }
    if (i < 256) g_stats[i] = 0.0f;
}

__global__ void hist_kernel(const int* __restrict__ aa_src, const int* __restrict__ aa_dst,
                            const float* __restrict__ len_aa,
                            const int* __restrict__ al_a, const int* __restrict__ al_l,
                            const float* __restrict__ len_al,
                            const float* __restrict__ w_e, const float* __restrict__ b_e) {
    int e = blockIdx.x * blockDim.x + threadIdx.x;
    if (e >= ETOT) return;
    int src, dst; float len;
    edge_decode(e, aa_src, aa_dst, len_aa, al_a, al_l, len_al, src, dst, len);
    float w = sigmoidf_(fmaf(len, w_e[0], b_e[0]));
    atomicAdd(&g_deg[dst], w);
    atomicAdd(&g_cnt[dst], 1);
}

// scan: rowptr/cursor only (R12 version — dinv kept separate on purpose)
__global__ __launch_bounds__(1024)
void scan_kernel() {
    __shared__ int ssum[1024];
    const int C = (N_TOT + 1023) / 1024;
    int t = threadIdx.x;
    int beg = t * C, end = min(beg + C, N_TOT);
    int s = 0;
    for (int i = beg; i < end; ++i) s += g_cnt[i];
    ssum[t] = s;
    __syncthreads();
    for (int off = 1; off < 1024; off <<= 1) {
        int v = (t >= off) ? ssum[t - off] : 0;
        __syncthreads();
        ssum[t] += v;
        __syncthreads();
    }
    int run = ssum[t] - s;
    for (int i = beg; i < end; ++i) {
        g_rowptr[i] = run;
        g_cursor[i] = run;
        run += g_cnt[i];
    }
    if (t == 1023) g_rowptr[N_TOT] = ETOT;
}

__global__ void dinv_kernel() {
    int i = blockIdx.x * blockDim.x + threadIdx.x;
    if (i >= N_TOT) return;
    float d = g_deg[i];
    g_dinv[i] = (d > 0.0f) ? rsqrtf(d) : 0.0f;
}

__global__ void scatter_kernel(const int* __restrict__ aa_src, const int* __restrict__ aa_dst,
                               const float* __restrict__ len_aa,
                               const int* __restrict__ al_a, const int* __restrict__ al_l,
                               const float* __restrict__ len_al,
                               const float* __restrict__ w_e, const float* __restrict__ b_e) {
    int e = blockIdx.x * blockDim.x + threadIdx.x;
    if (e >= ETOT) return;
    int src, dst; float len;
    edge_decode(e, aa_src, aa_dst, len_aa, al_a, al_l, len_al, src, dst, len);
    float w = sigmoidf_(fmaf(len, w_e[0], b_e[0]));
    float nrm = g_dinv[src] * w * g_dinv[dst];
    int pos = atomicAdd(&g_cursor[dst], 1);
    g_epack[pos] = make_int2(src, __float_as_int(nrm));
}

// ---------------------------------------------------------------------------
__global__ __launch_bounds__(256)
void lin_kernel(const float* __restrict__ W, int in_sel, int use_bn) {
    __shared__ float Ws[64 * 65];
    __shared__ float xsh[64 * 65];
    const float* in = in_sel ? g_out1 : g_x;

    int tid = threadIdx.x;
    for (int idx = tid; idx < 64 * 64; idx += 256) {
        int k = idx >> 6, j = idx & 63;
        Ws[k * 65 + j] = W[idx];
    }
    int base = blockIdx.x * 64;
    for (int idx = tid; idx < 64 * 64; idx += 256) {
        int r = idx >> 6, k = idx & 63;
        int row = base + r;
        float v = (row < N_TOT) ? in[(size_t)row * 64 + k] : 0.0f;
        if (use_bn) v = fmaxf(fmaf(v, g_stats[128 + k], g_stats[192 + k]), 0.0f);
        xsh[r * 65 + k] = v;
    }
    __syncthreads();

    int j = tid & 63, rl = tid >> 6;
    for (int rr = rl; rr < 64; rr += 4) {
        float a = 0.0f;
#pragma unroll
        for (int k = 0; k < 64; ++k) a = fmaf(xsh[rr * 65 + k], Ws[k * 65 + j], a);
        int row = base + rr;
        if (row < N_TOT) g_h[(size_t)row * 64 + j] = a;
    }
}

// ---------------------------------------------------------------------------
// CSR aggregation, unroll-4 for MLP
// ---------------------------------------------------------------------------
__global__ __launch_bounds__(256)
void agg_csr_kernel(const float* __restrict__ bvec, float* __restrict__ dout, int map) {
    int node = blockIdx.x * 8 + (threadIdx.x >> 5);
    if (node >= N_TOT) return;
    int lane = threadIdx.x & 31;

    int beg = g_rowptr[node], end = g_rowptr[node + 1];

    float ax = 0.0f, ay = 0.0f;
    int e = beg;
    for (; e + 3 < end; e += 4) {
        int2 p0 = g_epack[e];
        int2 p1 = g_epack[e + 1];
        int2 p2 = g_epack[e + 2];
        int2 p3 = g_epack[e + 3];
        float2 v0 = *(const float2*)&g_h[(size_t)p0.x * 64 + 2 * lane];
        float2 v1 = *(const float2*)&g_h[(size_t)p1.x * 64 + 2 * lane];
        float2 v2 = *(const float2*)&g_h[(size_t)p2.x * 64 + 2 * lane];
        float2 v3 = *(const float2*)&g_h[(size_t)p3.x * 64 + 2 * lane];
        float n0 = __int_as_float(p0.y), n1 = __int_as_float(p1.y);
        float n2 = __int_as_float(p2.y), n3 = __int_as_float(p3.y);
        ax = fmaf(v0.x, n0, ax); ay = fmaf(v0.y, n0, ay);
        ax = fmaf(v1.x, n1, ax); ay = fmaf(v1.y, n1, ay);
        ax = fmaf(v2.x, n2, ax); ay = fmaf(v2.y, n2, ay);
        ax = fmaf(v3.x, n3, ax); ay = fmaf(v3.y, n3, ay);
    }
    for (; e < end; ++e) {
        int2 p0 = g_epack[e];
        float2 v0 = *(const float2*)&g_h[(size_t)p0.x * 64 + 2 * lane];
        float n0 = __int_as_float(p0.y);
        ax = fmaf(v0.x, n0, ax); ay = fmaf(v0.y, n0, ay);
    }

    float di = g_dinv[node];
    float dd = di * di;
    float2 hv = *(const float2*)&g_h[(size_t)node * 64 + 2 * lane];
    float2 bv = *(const float2*)&bvec[2 * lane];
    float2 res;
    res.x = fmaf(hv.x, dd, ax) + bv.x;
    res.y = fmaf(hv.y, dd, ay) + bv.y;

    float* op;
    if (map) {
        size_t off = (node < A_TOT) ? ((size_t)(A_TOT + node) * 64)
                                    : ((size_t)(A_TOT + L_TOT + node) * 64);
        op = dout + off;
    } else {
        op = g_out1 + (size_t)node * 64;
    }
    *(float2*)(op + 2 * lane) = res;
}

// ---------------------------------------------------------------------------
__global__ __launch_bounds__(256)
void bn_stats_kernel() {
    __shared__ float sh[512];
    int tid = threadIdx.x;
    int j = tid & 63;
    float s = 0.0f, s2 = 0.0f;
    for (int row = blockIdx.x * 4 + (tid >> 6); row < N_TOT; row += gridDim.x * 4) {
        float v = g_out1[(size_t)row * 64 + j];
        s += v; s2 += v * v;
    }
    sh[tid] = s; sh[256 + tid] = s2;
    __syncthreads();
    if (tid < 64) {
        float t = sh[tid] + sh[tid + 64] + sh[tid + 128] + sh[tid + 192];
        atomicAdd(&g_stats[tid], t);
    } else if (tid < 128) {
        int jj = tid - 64;
        float t = sh[256 + jj] + sh[256 + jj + 64] + sh[256 + jj + 128] + sh[256 + jj + 192];
        atomicAdd(&g_stats[64 + jj], t);
    }
}

__global__ void bn_final_kernel(const float* __restrict__ gamma, const float* __restrict__ beta) {
    int j = threadIdx.x;
    if (j >= 64) return;
    float mean = g_stats[j] * (1.0f / N_TOT);
    float var  = g_stats[64 + j] * (1.0f / N_TOT) - mean * mean;
    float rs   = rsqrtf(var + BN_EPS);
    float sc   = rs * gamma[j];
    g_stats[128 + j] = sc;
    g_stats[192 + j] = beta[j] - mean * sc;
}

// ---------------------------------------------------------------------------
extern "C" void kernel_launch(void* const* d_in, const int* in_sizes, int n_in,
                              void* d_out, int out_size) {
    const float* agent_hist = (const float*)d_in[0];
    const float* lane_nodes = (const float*)d_in[1];
    const int*   eaa        = (const int*)d_in[2];
    const float* len_aa     = (const float*)d_in[3];
    const int*   eal        = (const int*)d_in[4];
    const float* len_al     = (const float*)d_in[5];
    const float* Wih_a      = (const float*)d_in[6];
    const float* Whh_a      = (const float*)d_in[7];
    const float* b_a        = (const float*)d_in[8];
    const float* Wih_l      = (const float*)d_in[9];
    const float* Whh_l      = (const float*)d_in[10];
    const float* b_l        = (const float*)d_in[11];
    const float* w_e        = (const float*)d_in[12];
    const float* b_e        = (const float*)d_in[13];
    const float* W1         = (const float*)d_in[14];
    const float* b1         = (const float*)d_in[15];
    const float* gamma1     = (const float*)d_in[16];
    const float* beta1      = (const float*)d_in[17];
    const float* W2         = (const float*)d_in[18];
    const float* b2         = (const float*)d_in[19];
    float* out = (float*)d_out;

    const int* aa_src = eaa;
    const int* aa_dst = eaa + E_AA;
    const int* al_a   = eal;
    const int* al_l   = eal + E_AL;

    cudaFuncSetAttribute((const void*)lstm_unified_kernel,
                         cudaFuncAttributeMaxDynamicSharedMemorySize, LSTM_SMEM);

    // launch order: unified LSTM at index 3 (ncu target)
    init_kernel<<<(N_TOT + 255) / 256, 256>>>();
    hist_kernel<<<(ETOT + 255) / 256, 256>>>(aa_src, aa_dst, len_aa, al_a, al_l, len_al, w_e, b_e);
    scan_kernel<<<1, 1024>>>();

    lstm_unified_kernel<<<AGENT_BLOCKS + LANE_BLOCKS, 512, LSTM_SMEM>>>(
        agent_hist, Wih_a, Whh_a, b_a, lane_nodes, Wih_l, Whh_l, b_l, out);

    dinv_kernel<<<(N_TOT + 255) / 256, 256>>>();
    scatter_kernel<<<(ETOT + 255) / 256, 256>>>(aa_src, aa_dst, len_aa, al_a, al_l, len_al, w_e, b_e);

    // conv1
    lin_kernel<<<(N_TOT + 63) / 64, 256>>>(W1, 0, 0);
    agg_csr_kernel<<<(N_TOT + 7) / 8, 256>>>(b1, out, 0);

    // BN
    bn_stats_kernel<<<512, 256>>>();
    bn_final_kernel<<<1, 64>>>(gamma1, beta1);

    // conv2
    lin_kernel<<<(N_TOT + 63) / 64, 256>>>(W2, 1, 1);
    agg_csr_kernel<<<(N_TOT + 7) / 8, 256>>>(b2, out, 1);
}

// round 16
// speedup vs baseline: 1.4051x; 1.2426x over previous
#include <cuda_runtime.h>
#include <cuda_bf16.h>
#include <cstdint>

// ---------------------------------------------------------------------------
// Problem constants
// ---------------------------------------------------------------------------
#define A_TOT 20000
#define L_TOT 80000
#define N_TOT 100000
#define E_AA  400000
#define E_AL  800000
#define ETOT  (E_AA + 2 * E_AL)
#define HDIM  64
#define BN_EPS 1e-5f
#define AGENT_BLOCKS ((A_TOT + 63) / 64)   // 313
#define LANE_BLOCKS  ((L_TOT + 63) / 64)   // 1250
#define SCAN_BLOCKS  ((N_TOT + 255) / 256) // 391

typedef unsigned long long u64;

// ---------------------------------------------------------------------------
// Scratch (device globals)
// ---------------------------------------------------------------------------
__device__ float g_x[N_TOT * HDIM];
__device__ float g_h[N_TOT * HDIM];
__device__ float g_out1[N_TOT * HDIM];
__device__ float g_deg[N_TOT];
__device__ float g_dinv[N_TOT];
__device__ float g_stats[256];
__device__ int   g_cnt[N_TOT];
__device__ int   g_rowptr[N_TOT + 1];
__device__ int   g_cursor[N_TOT];
__device__ int   g_bsum[512];
__device__ int   g_bbase[512];
__device__ int2  g_epack[ETOT];

// ---------------------------------------------------------------------------
// math helpers
// ---------------------------------------------------------------------------
__device__ __forceinline__ float sigmoidf_(float x) {
    return 1.0f / (1.0f + __expf(-x));
}
__device__ __forceinline__ float tanh_fast(float x) {
    float y;
    asm("tanh.approx.f32 %0, %1;" : "=f"(y) : "f"(x));
    return y;
}
__device__ __forceinline__ float sig_fast(float x) {
    return fmaf(0.5f, tanh_fast(0.5f * x), 0.5f);
}
__device__ __forceinline__ void mma_bf16(float* d, const uint32_t* a,
                                         uint32_t b0, uint32_t b1) {
    asm volatile(
        "mma.sync.aligned.m16n8k16.row.col.f32.bf16.bf16.f32 "
        "{%0,%1,%2,%3}, {%4,%5,%6,%7}, {%8,%9}, {%0,%1,%2,%3};"
        : "+f"(d[0]), "+f"(d[1]), "+f"(d[2]), "+f"(d[3])
        : "r"(a[0]), "r"(a[1]), "r"(a[2]), "r"(a[3]), "r"(b0), "r"(b1));
}
#define LDSM4(r, addr)                                                        \
    asm volatile("ldmatrix.sync.aligned.m8n8.x4.shared.b16 {%0,%1,%2,%3}, [%4];" \
        : "=r"((r)[0]), "=r"((r)[1]), "=r"((r)[2]), "=r"((r)[3]) : "r"(addr))
#define BAR_GRP(id)                                                           \
    asm volatile("bar.sync %0, 256;" :: "r"(id) : "memory")

__device__ __forceinline__ uint32_t smem_u32(const void* p) {
    uint32_t a;
    asm("{ .reg .u64 t; cvta.to.shared.u64 t, %1; cvt.u32.u64 %0, t; }"
        : "=r"(a) : "l"(p));
    return a;
}
__device__ __forceinline__ uint32_t pack_bf2(float a, float b) {
    __nv_bfloat16 ha = __float2bfloat16(a), hb = __float2bfloat16(b);
    return (uint32_t)__bfloat16_as_ushort(ha) |
           ((uint32_t)__bfloat16_as_ushort(hb) << 16);
}
__device__ __forceinline__ float bf_lo(uint32_t v) {
    return __bfloat162float(__ushort_as_bfloat16((unsigned short)(v & 0xFFFF)));
}
__device__ __forceinline__ float bf_hi(uint32_t v) {
    return __bfloat162float(__ushort_as_bfloat16((unsigned short)(v >> 16)));
}

// ---------------------------------------------------------------------------
// LSTM body (device function) — unchanged from the 799us kernel.
// ---------------------------------------------------------------------------
#define ASTR 592
#define BSTRB 304
#define SM_B_OFF (64 * ASTR)
#define LSTM_SMEM (64 * ASTR + 256 * BSTRB)         // 115,712 B

template <int T, int D, bool MEAN>
__device__ __forceinline__ void lstm_body(
    char* smem,
    const float* __restrict__ xin,
    const float* __restrict__ Wih,
    const float* __restrict__ Whh,
    const float* __restrict__ bias,
    float* __restrict__ emb_out,
    int xnode_off, int nrows, int base)
{
    constexpr int TD = T * D;
    uint32_t* Aw = (uint32_t*)smem;
    const uint32_t sb = smem_u32(smem);

    const int tid  = threadIdx.x;
    const int wid  = tid >> 5, lane = tid & 31;
    const int lrow = lane >> 2, q = lane & 3;
    const int wm = wid >> 3, wn = wid & 7;

    for (int i = tid; i < 64 * (ASTR / 4) + 256 * (BSTRB / 4); i += 512) Aw[i] = 0;
    __syncthreads();

    for (int idx = tid; idx < 256 * 64; idx += 512) {
        int j = idx >> 6, k = idx & 63;
        int g = j >> 6, u = j & 63;
        int n = ((u >> 3) << 5) + (g << 3) + (u & 7);
        float w = Whh[idx];
        __nv_bfloat16 hi = __float2bfloat16(w);
        __nv_bfloat16 lo = __float2bfloat16(w - __bfloat162float(hi));
        char* bp = smem + SM_B_OFF + n * BSTRB;
        *(__nv_bfloat16*)(bp + 2 * k)       = hi;
        *(__nv_bfloat16*)(bp + 128 + 2 * k) = lo;
    }
    if (tid < 256) {
        int j = tid;
        int g = j >> 6, u = j & 63;
        int n = ((u >> 3) << 5) + (g << 3) + (u & 7);
        char* bp = smem + SM_B_OFF + n * BSTRB + 256;
#pragma unroll
        for (int d = 0; d < D; ++d) {
            float w = Wih[j * D + d];
            __nv_bfloat16 hi = __float2bfloat16(w);
            __nv_bfloat16 lo = __float2bfloat16(w - __bfloat162float(hi));
            *(__nv_bfloat16*)(bp + 2 * d)           = hi;
            *(__nv_bfloat16*)(bp + 2 * (D + d))     = hi;
            *(__nv_bfloat16*)(bp + 2 * (2 * D + d)) = lo;
        }
        *(__nv_bfloat16*)(bp + 2 * (3 * D)) = __float2bfloat16(bias[j]);
    }
    if (tid < 64) {
        char* ap = smem + tid * ASTR;
        *(__nv_bfloat16*)(ap + 512 + 2 * (3 * D)) = __float2bfloat16(1.0f);
        *(__nv_bfloat16*)(ap + 544 + 2 * (3 * D)) = __float2bfloat16(1.0f);
    }
    if (tid < 192) {
        int r = tid & 63, part = tid >> 6;
        char* ap = smem + r * ASTR + 512;
        bool ok = (base + r < nrows);
        const float* xr = xin + (size_t)(base + r) * TD;
#pragma unroll
        for (int d = 0; d < D; ++d) {
            float v = ok ? xr[d] : 0.0f;
            __nv_bfloat16 hi = __float2bfloat16(v);
            if (part == 0)      *(__nv_bfloat16*)(ap + 2 * d) = hi;
            else if (part == 1) *(__nv_bfloat16*)(ap + 2 * (D + d)) =
                                    __float2bfloat16(v - __bfloat162float(hi));
            else                *(__nv_bfloat16*)(ap + 2 * (2 * D + d)) = hi;
        }
    }
    __syncthreads();

    const uint32_t aAddr0 = sb + (uint32_t)(wm * 32 + (lane & 15)) * ASTR
                          + (uint32_t)((lane >> 4) * 8) * 2;
    const uint32_t bAddr0 = sb + SM_B_OFF
                          + (uint32_t)(wn * 32 + (lane >> 4) * 8 + (lane & 7)) * BSTRB
                          + (uint32_t)(((lane >> 3) & 1)) * 16;

    const int gl = tid & 255;
    const int xpart = gl >> 5;
    const int xrow  = wm * 32 + (gl & 31);

    float cst[8], outv[8];
#pragma unroll
    for (int i = 0; i < 8; ++i) { cst[i] = 0.0f; outv[i] = 0.0f; }

#pragma unroll 1
    for (int t = 0; t < T; ++t) {
        const uint32_t rb = (uint32_t)(t & 1);
        const uint32_t wbuf = rb ^ 1u;
        const uint32_t hbase = rb * 256u;
        const uint32_t xoff  = 512u + rb * 32u;

        float acc[2][4][4];
#pragma unroll
        for (int mt = 0; mt < 2; ++mt)
#pragma unroll
            for (int nt = 0; nt < 4; ++nt)
#pragma unroll
                for (int i = 0; i < 4; ++i) acc[mt][nt][i] = 0.0f;

        if (t > 0) {
#pragma unroll
            for (int ks = 0; ks < 4; ++ks) {
                const uint32_t ka = hbase + ks * 32;
                const uint32_t kb = ks * 32;
                uint32_t a0[4], a1[4], q0[4], q1[4];
                LDSM4(q0, bAddr0 + kb);
                LDSM4(q1, bAddr0 + 16 * BSTRB + kb);
                LDSM4(a0, aAddr0 + ka);
                LDSM4(a1, aAddr0 + 16 * ASTR + ka);
                mma_bf16(acc[0][0], a0, q0[0], q0[1]);
                mma_bf16(acc[0][1], a0, q0[2], q0[3]);
                mma_bf16(acc[0][2], a0, q1[0], q1[1]);
                mma_bf16(acc[0][3], a0, q1[2], q1[3]);
                mma_bf16(acc[1][0], a1, q0[0], q0[1]);
                mma_bf16(acc[1][1], a1, q0[2], q0[3]);
                mma_bf16(acc[1][2], a1, q1[0], q1[1]);
                mma_bf16(acc[1][3], a1, q1[2], q1[3]);
                LDSM4(a0, aAddr0 + ka + 128);
                LDSM4(a1, aAddr0 + 16 * ASTR + ka + 128);
                mma_bf16(acc[0][0], a0, q0[0], q0[1]);
                mma_bf16(acc[0][1], a0, q0[2], q0[3]);
                mma_bf16(acc[0][2], a0, q1[0], q1[1]);
                mma_bf16(acc[0][3], a0, q1[2], q1[3]);
                mma_bf16(acc[1][0], a1, q0[0], q0[1]);
                mma_bf16(acc[1][1], a1, q0[2], q0[3]);
                mma_bf16(acc[1][2], a1, q1[0], q1[1]);
                mma_bf16(acc[1][3], a1, q1[2], q1[3]);
                LDSM4(q0, bAddr0 + kb + 128);
                LDSM4(q1, bAddr0 + 16 * BSTRB + kb + 128);
                LDSM4(a0, aAddr0 + ka);
                LDSM4(a1, aAddr0 + 16 * ASTR + ka);
                mma_bf16(acc[0][0], a0, q0[0], q0[1]);
                mma_bf16(acc[0][1], a0, q0[2], q0[3]);
                mma_bf16(acc[0][2], a0, q1[0], q1[1]);
                mma_bf16(acc[0][3], a0, q1[2], q1[3]);
                mma_bf16(acc[1][0], a1, q0[0], q0[1]);
                mma_bf16(acc[1][1], a1, q0[2], q0[3]);
                mma_bf16(acc[1][2], a1, q1[0], q1[1]);
                mma_bf16(acc[1][3], a1, q1[2], q1[3]);
            }
        }
        {
            uint32_t a0[4], a1[4], q0[4], q1[4];
            LDSM4(a0, aAddr0 + xoff);
            LDSM4(a1, aAddr0 + 16 * ASTR + xoff);
            LDSM4(q0, bAddr0 + 256);
            LDSM4(q1, bAddr0 + 16 * BSTRB + 256);
            mma_bf16(acc[0][0], a0, q0[0], q0[1]);
            mma_bf16(acc[0][1], a0, q0[2], q0[3]);
            mma_bf16(acc[0][2], a0, q1[0], q1[1]);
            mma_bf16(acc[0][3], a0, q1[2], q1[3]);
            mma_bf16(acc[1][0], a1, q0[0], q0[1]);
            mma_bf16(acc[1][1], a1, q0[2], q0[3]);
            mma_bf16(acc[1][2], a1, q1[0], q1[1]);
            mma_bf16(acc[1][3], a1, q1[2], q1[3]);
        }

#pragma unroll
        for (int mt = 0; mt < 2; ++mt)
#pragma unroll
            for (int half = 0; half < 2; ++half) {
                float hpair[2];
#pragma unroll
                for (int jp = 0; jp < 2; ++jp) {
                    int rg = half * 2 + jp;
                    float gi = acc[mt][0][rg];
                    float gf = acc[mt][1][rg];
                    float gg = acc[mt][2][rg];
                    float go = acc[mt][3][rg];
                    int ci = mt * 4 + half * 2 + jp;
                    float cn = fmaf(sig_fast(gf), cst[ci],
                                    sig_fast(gi) * tanh_fast(gg));
                    cst[ci] = cn;
                    float h = sig_fast(go) * tanh_fast(cn);
                    if (MEAN) outv[ci] += h;
                    hpair[jp] = h;
                }
                __nv_bfloat16 h0 = __float2bfloat16(hpair[0]);
                __nv_bfloat16 h1 = __float2bfloat16(hpair[1]);
                uint32_t hi2 = (uint32_t)__bfloat16_as_ushort(h0) |
                               ((uint32_t)__bfloat16_as_ushort(h1) << 16);
                uint32_t lo2 = pack_bf2(hpair[0] - __bfloat162float(h0),
                                        hpair[1] - __bfloat162float(h1));
                int row = wm * 32 + mt * 16 + half * 8 + lrow;
                int uw  = wn * 4 + q;
                Aw[row * (ASTR / 4) + wbuf * 64 + uw]      = hi2;
                Aw[row * (ASTR / 4) + wbuf * 64 + 32 + uw] = lo2;
            }

        if (t + 1 < T && xpart < 3) {
            char* ap = smem + xrow * ASTR + 512 + wbuf * 32;
            bool ok = (base + xrow < nrows);
            const float* xr = xin + (size_t)(base + xrow) * TD + (t + 1) * D;
#pragma unroll
            for (int d = 0; d < D; ++d) {
                float v = ok ? xr[d] : 0.0f;
                __nv_bfloat16 hi = __float2bfloat16(v);
                if (xpart == 0)      *(__nv_bfloat16*)(ap + 2 * d) = hi;
                else if (xpart == 1) *(__nv_bfloat16*)(ap + 2 * (D + d)) =
                                         __float2bfloat16(v - __bfloat162float(hi));
                else                 *(__nv_bfloat16*)(ap + 2 * (2 * D + d)) = hi;
            }
        }
        BAR_GRP(1 + wm);
    }

    const float scale = MEAN ? (1.0f / T) : 1.0f;
    const uint32_t fb = (uint32_t)(T & 1);
#pragma unroll
    for (int mt = 0; mt < 2; ++mt)
#pragma unroll
        for (int half = 0; half < 2; ++half) {
            int row = wm * 32 + mt * 16 + half * 8 + lrow;
            int grow = base + row;
            if (grow >= nrows) continue;
            int unit0 = wn * 8 + 2 * q;
            float2 v;
            if (MEAN) {
                int ci0 = mt * 4 + half * 2;
                v = make_float2(outv[ci0] * scale, outv[ci0 + 1] * scale);
            } else {
                uint32_t hi2 = Aw[row * (ASTR / 4) + fb * 64 + wn * 4 + q];
                uint32_t lo2 = Aw[row * (ASTR / 4) + fb * 64 + 32 + wn * 4 + q];
                v = make_float2(bf_lo(hi2) + bf_lo(lo2), bf_hi(hi2) + bf_hi(lo2));
            }
            *(float2*)&emb_out[(size_t)grow * 64 + unit0] = v;
            *(float2*)&g_x[(size_t)(xnode_off + grow) * 64 + unit0] = v;
        }
}

__global__ __launch_bounds__(512, 2)
void lstm_unified_kernel(const float* __restrict__ agent_hist,
                         const float* __restrict__ Wih_a,
                         const float* __restrict__ Whh_a,
                         const float* __restrict__ b_a,
                         const float* __restrict__ lane_nodes,
                         const float* __restrict__ Wih_l,
                         const float* __restrict__ Whh_l,
                         const float* __restrict__ b_l,
                         float* __restrict__ out)
{
    extern __shared__ char smem[];
    if (blockIdx.x < AGENT_BLOCKS) {
        lstm_body<20, 5, false>(smem, agent_hist, Wih_a, Whh_a, b_a,
                                out, 0, A_TOT, blockIdx.x * 64);
    } else {
        lstm_body<10, 2, true>(smem, lane_nodes, Wih_l, Whh_l, b_l,
                               out + (size_t)2 * A_TOT * 64, A_TOT, L_TOT,
                               (blockIdx.x - AGENT_BLOCKS) * 64);
    }
}

// ---------------------------------------------------------------------------
// edge decode + CSR build
// ---------------------------------------------------------------------------
__device__ __forceinline__ void edge_decode(
    int e,
    const int* __restrict__ aa_src, const int* __restrict__ aa_dst,
    const float* __restrict__ len_aa,
    const int* __restrict__ al_a, const int* __restrict__ al_l,
    const float* __restrict__ len_al,
    int& src, int& dst, float& len)
{
    if (e < E_AA) {
        src = aa_src[e]; dst = aa_dst[e]; len = len_aa[e];
    } else if (e < E_AA + E_AL) {
        int i = e - E_AA;
        src = al_a[i]; dst = A_TOT + al_l[i]; len = len_al[i];
    } else {
        int i = e - E_AA - E_AL;
        src = A_TOT + al_l[i]; dst = al_a[i]; len = len_al[i];
    }
}

__global__ void init_kernel() {
    int i = blockIdx.x * blockDim.x + threadIdx.x;
    if (i < N_TOT) { g_deg[i] = 1.0f; g_cnt[i] = 0; }
    if (i < 256) g_stats[i] = 0.0f;
}

__global__ void hist_kernel(const int* __restrict__ aa_src, const int* __restrict__ aa_dst,
                            const float* __restrict__ len_aa,
                            const int* __restrict__ al_a, const int* __restrict__ al_l,
                            const float* __restrict__ len_al,
                            const float* __restrict__ w_e, const float* __restrict__ b_e) {
    int e = blockIdx.x * blockDim.x + threadIdx.x;
    if (e >= ETOT) return;
    int src, dst; float len;
    edge_decode(e, aa_src, aa_dst, len_aa, al_a, al_l, len_al, src, dst, len);
    float w = sigmoidf_(fmaf(len, w_e[0], b_e[0]));
    atomicAdd(&g_deg[dst], w);
    atomicAdd(&g_cnt[dst], 1);
}

// ---- parallel 3-phase scan -------------------------------------------------
__global__ __launch_bounds__(256)
void scan1_kernel() {
    __shared__ int sh[256];
    int i = blockIdx.x * 256 + threadIdx.x;
    sh[threadIdx.x] = (i < N_TOT) ? g_cnt[i] : 0;
    __syncthreads();
    for (int off = 128; off > 0; off >>= 1) {
        if (threadIdx.x < off) sh[threadIdx.x] += sh[threadIdx.x + off];
        __syncthreads();
    }
    if (threadIdx.x == 0) g_bsum[blockIdx.x] = sh[0];
}

__global__ __launch_bounds__(512)
void scan2_kernel() {
    __shared__ int sh[512];
    int t = threadIdx.x;
    int v = (t < SCAN_BLOCKS) ? g_bsum[t] : 0;
    sh[t] = v;
    __syncthreads();
    for (int off = 1; off < 512; off <<= 1) {
        int u = (t >= off) ? sh[t - off] : 0;
        __syncthreads();
        sh[t] += u;
        __syncthreads();
    }
    if (t < SCAN_BLOCKS) g_bbase[t] = sh[t] - v;   // exclusive
    if (t == 0) g_rowptr[N_TOT] = ETOT;
}

__global__ __launch_bounds__(256)
void scan3_kernel() {
    __shared__ int sh[256];
    int i = blockIdx.x * 256 + threadIdx.x;
    int t = threadIdx.x;
    int v = (i < N_TOT) ? g_cnt[i] : 0;
    sh[t] = v;
    __syncthreads();
    for (int off = 1; off < 256; off <<= 1) {
        int u = (t >= off) ? sh[t - off] : 0;
        __syncthreads();
        sh[t] += u;
        __syncthreads();
    }
    if (i < N_TOT) {
        int excl = g_bbase[blockIdx.x] + sh[t] - v;
        g_rowptr[i] = excl;
        g_cursor[i] = excl;
        float d = g_deg[i];
        g_dinv[i] = (d > 0.0f) ? rsqrtf(d) : 0.0f;
    }
}

__global__ void scatter_kernel(const int* __restrict__ aa_src, const int* __restrict__ aa_dst,
                               const float* __restrict__ len_aa,
                               const int* __restrict__ al_a, const int* __restrict__ al_l,
                               const float* __restrict__ len_al,
                               const float* __restrict__ w_e, const float* __restrict__ b_e) {
    int e = blockIdx.x * blockDim.x + threadIdx.x;
    if (e >= ETOT) return;
    int src, dst; float len;
    edge_decode(e, aa_src, aa_dst, len_aa, al_a, al_l, len_al, src, dst, len);
    float w = sigmoidf_(fmaf(len, w_e[0], b_e[0]));
    float nrm = g_dinv[src] * w * g_dinv[dst];
    int pos = atomicAdd(&g_cursor[dst], 1);
    g_epack[pos] = make_int2(src, __float_as_int(nrm));
}

// ---------------------------------------------------------------------------
__global__ __launch_bounds__(256)
void lin_kernel(const float* __restrict__ W, int in_sel, int use_bn) {
    __shared__ float Ws[64 * 65];
    __shared__ float xsh[64 * 65];
    const float* in = in_sel ? g_out1 : g_x;

    int tid = threadIdx.x;
    for (int idx = tid; idx < 64 * 64; idx += 256) {
        int k = idx >> 6, j = idx & 63;
        Ws[k * 65 + j] = W[idx];
    }
    int base = blockIdx.x * 64;
    for (int idx = tid; idx < 64 * 64; idx += 256) {
        int r = idx >> 6, k = idx & 63;
        int row = base + r;
        float v = (row < N_TOT) ? in[(size_t)row * 64 + k] : 0.0f;
        if (use_bn) v = fmaxf(fmaf(v, g_stats[128 + k], g_stats[192 + k]), 0.0f);
        xsh[r * 65 + k] = v;
    }
    __syncthreads();

    int j = tid & 63, rl = tid >> 6;
    for (int rr = rl; rr < 64; rr += 4) {
        float a = 0.0f;
#pragma unroll
        for (int k = 0; k < 64; ++k) a = fmaf(xsh[rr * 65 + k], Ws[k * 65 + j], a);
        int row = base + rr;
        if (row < N_TOT) g_h[(size_t)row * 64 + j] = a;
    }
}

// ---------------------------------------------------------------------------
__global__ __launch_bounds__(256)
void agg_csr_kernel(const float* __restrict__ bvec, float* __restrict__ dout, int map) {
    int node = blockIdx.x * 8 + (threadIdx.x >> 5);
    if (node >= N_TOT) return;
    int lane = threadIdx.x & 31;

    int beg = g_rowptr[node], end = g_rowptr[node + 1];

    float ax = 0.0f, ay = 0.0f;
    int e = beg;
    for (; e + 3 < end; e += 4) {
        int2 p0 = g_epack[e];
        int2 p1 = g_epack[e + 1];
        int2 p2 = g_epack[e + 2];
        int2 p3 = g_epack[e + 3];
        float2 v0 = *(const float2*)&g_h[(size_t)p0.x * 64 + 2 * lane];
        float2 v1 = *(const float2*)&g_h[(size_t)p1.x * 64 + 2 * lane];
        float2 v2 = *(const float2*)&g_h[(size_t)p2.x * 64 + 2 * lane];
        float2 v3 = *(const float2*)&g_h[(size_t)p3.x * 64 + 2 * lane];
        float n0 = __int_as_float(p0.y), n1 = __int_as_float(p1.y);
        float n2 = __int_as_float(p2.y), n3 = __int_as_float(p3.y);
        ax = fmaf(v0.x, n0, ax); ay = fmaf(v0.y, n0, ay);
        ax = fmaf(v1.x, n1, ax); ay = fmaf(v1.y, n1, ay);
        ax = fmaf(v2.x, n2, ax); ay = fmaf(v2.y, n2, ay);
        ax = fmaf(v3.x, n3, ax); ay = fmaf(v3.y, n3, ay);
    }
    for (; e < end; ++e) {
        int2 p0 = g_epack[e];
        float2 v0 = *(const float2*)&g_h[(size_t)p0.x * 64 + 2 * lane];
        float n0 = __int_as_float(p0.y);
        ax = fmaf(v0.x, n0, ax); ay = fmaf(v0.y, n0, ay);
    }

    float di = g_dinv[node];
    float dd = di * di;
    float2 hv = *(const float2*)&g_h[(size_t)node * 64 + 2 * lane];
    float2 bv = *(const float2*)&bvec[2 * lane];
    float2 res;
    res.x = fmaf(hv.x, dd, ax) + bv.x;
    res.y = fmaf(hv.y, dd, ay) + bv.y;

    float* op;
    if (map) {
        size_t off = (node < A_TOT) ? ((size_t)(A_TOT + node) * 64)
                                    : ((size_t)(A_TOT + L_TOT + node) * 64);
        op = dout + off;
    } else {
        op = g_out1 + (size_t)node * 64;
    }
    *(float2*)(op + 2 * lane) = res;
}

// ---------------------------------------------------------------------------
__global__ __launch_bounds__(256)
void bn_stats_kernel() {
    __shared__ float sh[512];
    int tid = threadIdx.x;
    int j = tid & 63;
    float s = 0.0f, s2 = 0.0f;
    for (int row = blockIdx.x * 4 + (tid >> 6); row < N_TOT; row += gridDim.x * 4) {
        float v = g_out1[(size_t)row * 64 + j];
        s += v; s2 += v * v;
    }
    sh[tid] = s; sh[256 + tid] = s2;
    __syncthreads();
    if (tid < 64) {
        float t = sh[tid] + sh[tid + 64] + sh[tid + 128] + sh[tid + 192];
        atomicAdd(&g_stats[tid], t);
    } else if (tid < 128) {
        int jj = tid - 64;
        float t = sh[256 + jj] + sh[256 + jj + 64] + sh[256 + jj + 128] + sh[256 + jj + 192];
        atomicAdd(&g_stats[64 + jj], t);
    }
}

__global__ void bn_final_kernel(const float* __restrict__ gamma, const float* __restrict__ beta) {
    int j = threadIdx.x;
    if (j >= 64) return;
    float mean = g_stats[j] * (1.0f / N_TOT);
    float var  = g_stats[64 + j] * (1.0f / N_TOT) - mean * mean;
    float rs   = rsqrtf(var + BN_EPS);
    float sc   = rs * gamma[j];
    g_stats[128 + j] = sc;
    g_stats[192 + j] = beta[j] - mean * sc;
}

// ---------------------------------------------------------------------------
extern "C" void kernel_launch(void* const* d_in, const int* in_sizes, int n_in,
                              void* d_out, int out_size) {
    const float* agent_hist = (const float*)d_in[0];
    const float* lane_nodes = (const float*)d_in[1];
    const int*   eaa        = (const int*)d_in[2];
    const float* len_aa     = (const float*)d_in[3];
    const int*   eal        = (const int*)d_in[4];
    const float* len_al     = (const float*)d_in[5];
    const float* Wih_a      = (const float*)d_in[6];
    const float* Whh_a      = (const float*)d_in[7];
    const float* b_a        = (const float*)d_in[8];
    const float* Wih_l      = (const float*)d_in[9];
    const float* Whh_l      = (const float*)d_in[10];
    const float* b_l        = (const float*)d_in[11];
    const float* w_e        = (const float*)d_in[12];
    const float* b_e        = (const float*)d_in[13];
    const float* W1         = (const float*)d_in[14];
    const float* b1         = (const float*)d_in[15];
    const float* gamma1     = (const float*)d_in[16];
    const float* beta1      = (const float*)d_in[17];
    const float* W2         = (const float*)d_in[18];
    const float* b2         = (const float*)d_in[19];
    float* out = (float*)d_out;

    const int* aa_src = eaa;
    const int* aa_dst = eaa + E_AA;
    const int* al_a   = eal;
    const int* al_l   = eal + E_AL;

    cudaFuncSetAttribute((const void*)lstm_unified_kernel,
                         cudaFuncAttributeMaxDynamicSharedMemorySize, LSTM_SMEM);

    init_kernel<<<(N_TOT + 255) / 256, 256>>>();
    hist_kernel<<<(ETOT + 255) / 256, 256>>>(aa_src, aa_dst, len_aa, al_a, al_l, len_al, w_e, b_e);
    scan1_kernel<<<SCAN_BLOCKS, 256>>>();

    lstm_unified_kernel<<<AGENT_BLOCKS + LANE_BLOCKS, 512, LSTM_SMEM>>>(
        agent_hist, Wih_a, Whh_a, b_a, lane_nodes, Wih_l, Whh_l, b_l, out);

    scan2_kernel<<<1, 512>>>();
    scan3_kernel<<<SCAN_BLOCKS, 256>>>();
    scatter_kernel<<<(ETOT + 255) / 256, 256>>>(aa_src, aa_dst, len_aa, al_a, al_l, len_al, w_e, b_e);

    // conv1
    lin_kernel<<<(N_TOT + 63) / 64, 256>>>(W1, 0, 0);
    agg_csr_kernel<<<(N_TOT + 7) / 8, 256>>>(b1, out, 0);

    // BN
    bn_stats_kernel<<<512, 256>>>();
    bn_final_kernel<<<1, 64>>>(gamma1, beta1);

    // conv2
    lin_kernel<<<(N_TOT + 63) / 64, 256>>>(W2, 1, 1);
    agg_csr_kernel<<<(N_TOT + 7) / 8, 256>>>(b2, out, 1);
}

// round 17
// speedup vs baseline: 1.4121x; 1.0050x over previous
#include <cuda_runtime.h>
#include <cuda_bf16.h>
#include <cstdint>

// ---------------------------------------------------------------------------
// Problem constants
// ---------------------------------------------------------------------------
#define A_TOT 20000
#define L_TOT 80000
#define N_TOT 100000
#define E_AA  400000
#define E_AL  800000
#define ETOT  (E_AA + 2 * E_AL)
#define HDIM  64
#define BN_EPS 1e-5f
#define AGENT_BLOCKS ((A_TOT + 63) / 64)   // 313
#define LANE_BLOCKS  ((L_TOT + 63) / 64)   // 1250
#define SCAN_BLOCKS  ((N_TOT + 255) / 256) // 391

typedef unsigned long long u64;

// ---------------------------------------------------------------------------
// Scratch (device globals)
// ---------------------------------------------------------------------------
__device__ float g_x[N_TOT * HDIM];
__device__ float g_h[N_TOT * HDIM];
__device__ float g_out1[N_TOT * HDIM];
__device__ float g_deg[N_TOT];
__device__ float g_dinv[N_TOT];
__device__ float g_stats[256];
__device__ int   g_cnt[N_TOT];
__device__ int   g_rowptr[N_TOT + 1];
__device__ int   g_cursor[N_TOT];
__device__ int   g_bsum[512];
__device__ int   g_bbase[512];
__device__ int2  g_epack[ETOT];

// ---------------------------------------------------------------------------
// math helpers
// ---------------------------------------------------------------------------
__device__ __forceinline__ float sigmoidf_(float x) {
    return 1.0f / (1.0f + __expf(-x));
}
__device__ __forceinline__ float tanh_fast(float x) {
    float y;
    asm("tanh.approx.f32 %0, %1;" : "=f"(y) : "f"(x));
    return y;
}
__device__ __forceinline__ float sig_fast(float x) {
    return fmaf(0.5f, tanh_fast(0.5f * x), 0.5f);
}
__device__ __forceinline__ void mma_bf16(float* d, const uint32_t* a,
                                         uint32_t b0, uint32_t b1) {
    asm volatile(
        "mma.sync.aligned.m16n8k16.row.col.f32.bf16.bf16.f32 "
        "{%0,%1,%2,%3}, {%4,%5,%6,%7}, {%8,%9}, {%0,%1,%2,%3};"
        : "+f"(d[0]), "+f"(d[1]), "+f"(d[2]), "+f"(d[3])
        : "r"(a[0]), "r"(a[1]), "r"(a[2]), "r"(a[3]), "r"(b0), "r"(b1));
}
#define LDSM4(r, addr)                                                        \
    asm volatile("ldmatrix.sync.aligned.m8n8.x4.shared.b16 {%0,%1,%2,%3}, [%4];" \
        : "=r"((r)[0]), "=r"((r)[1]), "=r"((r)[2]), "=r"((r)[3]) : "r"(addr))
#define BAR_GRP(id)                                                           \
    asm volatile("bar.sync %0, 256;" :: "r"(id) : "memory")

__device__ __forceinline__ uint32_t smem_u32(const void* p) {
    uint32_t a;
    asm("{ .reg .u64 t; cvta.to.shared.u64 t, %1; cvt.u32.u64 %0, t; }"
        : "=r"(a) : "l"(p));
    return a;
}
__device__ __forceinline__ uint32_t pack_bf2(float a, float b) {
    __nv_bfloat16 ha = __float2bfloat16(a), hb = __float2bfloat16(b);
    return (uint32_t)__bfloat16_as_ushort(ha) |
           ((uint32_t)__bfloat16_as_ushort(hb) << 16);
}
__device__ __forceinline__ float bf_lo(uint32_t v) {
    return __bfloat162float(__ushort_as_bfloat16((unsigned short)(v & 0xFFFF)));
}
__device__ __forceinline__ float bf_hi(uint32_t v) {
    return __bfloat162float(__ushort_as_bfloat16((unsigned short)(v >> 16)));
}

// ---------------------------------------------------------------------------
// LSTM body (device function) — unchanged from the 643us kernel.
// ---------------------------------------------------------------------------
#define ASTR 592
#define BSTRB 304
#define SM_B_OFF (64 * ASTR)
#define LSTM_SMEM (64 * ASTR + 256 * BSTRB)         // 115,712 B

template <int T, int D, bool MEAN>
__device__ __forceinline__ void lstm_body(
    char* smem,
    const float* __restrict__ xin,
    const float* __restrict__ Wih,
    const float* __restrict__ Whh,
    const float* __restrict__ bias,
    float* __restrict__ emb_out,
    int xnode_off, int nrows, int base)
{
    constexpr int TD = T * D;
    uint32_t* Aw = (uint32_t*)smem;
    const uint32_t sb = smem_u32(smem);

    const int tid  = threadIdx.x;
    const int wid  = tid >> 5, lane = tid & 31;
    const int lrow = lane >> 2, q = lane & 3;
    const int wm = wid >> 3, wn = wid & 7;

    for (int i = tid; i < 64 * (ASTR / 4) + 256 * (BSTRB / 4); i += 512) Aw[i] = 0;
    __syncthreads();

    for (int idx = tid; idx < 256 * 64; idx += 512) {
        int j = idx >> 6, k = idx & 63;
        int g = j >> 6, u = j & 63;
        int n = ((u >> 3) << 5) + (g << 3) + (u & 7);
        float w = Whh[idx];
        __nv_bfloat16 hi = __float2bfloat16(w);
        __nv_bfloat16 lo = __float2bfloat16(w - __bfloat162float(hi));
        char* bp = smem + SM_B_OFF + n * BSTRB;
        *(__nv_bfloat16*)(bp + 2 * k)       = hi;
        *(__nv_bfloat16*)(bp + 128 + 2 * k) = lo;
    }
    if (tid < 256) {
        int j = tid;
        int g = j >> 6, u = j & 63;
        int n = ((u >> 3) << 5) + (g << 3) + (u & 7);
        char* bp = smem + SM_B_OFF + n * BSTRB + 256;
#pragma unroll
        for (int d = 0; d < D; ++d) {
            float w = Wih[j * D + d];
            __nv_bfloat16 hi = __float2bfloat16(w);
            __nv_bfloat16 lo = __float2bfloat16(w - __bfloat162float(hi));
            *(__nv_bfloat16*)(bp + 2 * d)           = hi;
            *(__nv_bfloat16*)(bp + 2 * (D + d))     = hi;
            *(__nv_bfloat16*)(bp + 2 * (2 * D + d)) = lo;
        }
        *(__nv_bfloat16*)(bp + 2 * (3 * D)) = __float2bfloat16(bias[j]);
    }
    if (tid < 64) {
        char* ap = smem + tid * ASTR;
        *(__nv_bfloat16*)(ap + 512 + 2 * (3 * D)) = __float2bfloat16(1.0f);
        *(__nv_bfloat16*)(ap + 544 + 2 * (3 * D)) = __float2bfloat16(1.0f);
    }
    if (tid < 192) {
        int r = tid & 63, part = tid >> 6;
        char* ap = smem + r * ASTR + 512;
        bool ok = (base + r < nrows);
        const float* xr = xin + (size_t)(base + r) * TD;
#pragma unroll
        for (int d = 0; d < D; ++d) {
            float v = ok ? xr[d] : 0.0f;
            __nv_bfloat16 hi = __float2bfloat16(v);
            if (part == 0)      *(__nv_bfloat16*)(ap + 2 * d) = hi;
            else if (part == 1) *(__nv_bfloat16*)(ap + 2 * (D + d)) =
                                    __float2bfloat16(v - __bfloat162float(hi));
            else                *(__nv_bfloat16*)(ap + 2 * (2 * D + d)) = hi;
        }
    }
    __syncthreads();

    const uint32_t aAddr0 = sb + (uint32_t)(wm * 32 + (lane & 15)) * ASTR
                          + (uint32_t)((lane >> 4) * 8) * 2;
    const uint32_t bAddr0 = sb + SM_B_OFF
                          + (uint32_t)(wn * 32 + (lane >> 4) * 8 + (lane & 7)) * BSTRB
                          + (uint32_t)(((lane >> 3) & 1)) * 16;

    const int gl = tid & 255;
    const int xpart = gl >> 5;
    const int xrow  = wm * 32 + (gl & 31);

    float cst[8], outv[8];
#pragma unroll
    for (int i = 0; i < 8; ++i) { cst[i] = 0.0f; outv[i] = 0.0f; }

#pragma unroll 1
    for (int t = 0; t < T; ++t) {
        const uint32_t rb = (uint32_t)(t & 1);
        const uint32_t wbuf = rb ^ 1u;
        const uint32_t hbase = rb * 256u;
        const uint32_t xoff  = 512u + rb * 32u;

        float acc[2][4][4];
#pragma unroll
        for (int mt = 0; mt < 2; ++mt)
#pragma unroll
            for (int nt = 0; nt < 4; ++nt)
#pragma unroll
                for (int i = 0; i < 4; ++i) acc[mt][nt][i] = 0.0f;

        if (t > 0) {
#pragma unroll
            for (int ks = 0; ks < 4; ++ks) {
                const uint32_t ka = hbase + ks * 32;
                const uint32_t kb = ks * 32;
                uint32_t a0[4], a1[4], q0[4], q1[4];
                LDSM4(q0, bAddr0 + kb);
                LDSM4(q1, bAddr0 + 16 * BSTRB + kb);
                LDSM4(a0, aAddr0 + ka);
                LDSM4(a1, aAddr0 + 16 * ASTR + ka);
                mma_bf16(acc[0][0], a0, q0[0], q0[1]);
                mma_bf16(acc[0][1], a0, q0[2], q0[3]);
                mma_bf16(acc[0][2], a0, q1[0], q1[1]);
                mma_bf16(acc[0][3], a0, q1[2], q1[3]);
                mma_bf16(acc[1][0], a1, q0[0], q0[1]);
                mma_bf16(acc[1][1], a1, q0[2], q0[3]);
                mma_bf16(acc[1][2], a1, q1[0], q1[1]);
                mma_bf16(acc[1][3], a1, q1[2], q1[3]);
                LDSM4(a0, aAddr0 + ka + 128);
                LDSM4(a1, aAddr0 + 16 * ASTR + ka + 128);
                mma_bf16(acc[0][0], a0, q0[0], q0[1]);
                mma_bf16(acc[0][1], a0, q0[2], q0[3]);
                mma_bf16(acc[0][2], a0, q1[0], q1[1]);
                mma_bf16(acc[0][3], a0, q1[2], q1[3]);
                mma_bf16(acc[1][0], a1, q0[0], q0[1]);
                mma_bf16(acc[1][1], a1, q0[2], q0[3]);
                mma_bf16(acc[1][2], a1, q1[0], q1[1]);
                mma_bf16(acc[1][3], a1, q1[2], q1[3]);
                LDSM4(q0, bAddr0 + kb + 128);
                LDSM4(q1, bAddr0 + 16 * BSTRB + kb + 128);
                LDSM4(a0, aAddr0 + ka);
                LDSM4(a1, aAddr0 + 16 * ASTR + ka);
                mma_bf16(acc[0][0], a0, q0[0], q0[1]);
                mma_bf16(acc[0][1], a0, q0[2], q0[3]);
                mma_bf16(acc[0][2], a0, q1[0], q1[1]);
                mma_bf16(acc[0][3], a0, q1[2], q1[3]);
                mma_bf16(acc[1][0], a1, q0[0], q0[1]);
                mma_bf16(acc[1][1], a1, q0[2], q0[3]);
                mma_bf16(acc[1][2], a1, q1[0], q1[1]);
                mma_bf16(acc[1][3], a1, q1[2], q1[3]);
            }
        }
        {
            uint32_t a0[4], a1[4], q0[4], q1[4];
            LDSM4(a0, aAddr0 + xoff);
            LDSM4(a1, aAddr0 + 16 * ASTR + xoff);
            LDSM4(q0, bAddr0 + 256);
            LDSM4(q1, bAddr0 + 16 * BSTRB + 256);
            mma_bf16(acc[0][0], a0, q0[0], q0[1]);
            mma_bf16(acc[0][1], a0, q0[2], q0[3]);
            mma_bf16(acc[0][2], a0, q1[0], q1[1]);
            mma_bf16(acc[0][3], a0, q1[2], q1[3]);
            mma_bf16(acc[1][0], a1, q0[0], q0[1]);
            mma_bf16(acc[1][1], a1, q0[2], q0[3]);
            mma_bf16(acc[1][2], a1, q1[0], q1[1]);
            mma_bf16(acc[1][3], a1, q1[2], q1[3]);
        }

#pragma unroll
        for (int mt = 0; mt < 2; ++mt)
#pragma unroll
            for (int half = 0; half < 2; ++half) {
                float hpair[2];
#pragma unroll
                for (int jp = 0; jp < 2; ++jp) {
                    int rg = half * 2 + jp;
                    float gi = acc[mt][0][rg];
                    float gf = acc[mt][1][rg];
                    float gg = acc[mt][2][rg];
                    float go = acc[mt][3][rg];
                    int ci = mt * 4 + half * 2 + jp;
                    float cn = fmaf(sig_fast(gf), cst[ci],
                                    sig_fast(gi) * tanh_fast(gg));
                    cst[ci] = cn;
                    float h = sig_fast(go) * tanh_fast(cn);
                    if (MEAN) outv[ci] += h;
                    hpair[jp] = h;
                }
                __nv_bfloat16 h0 = __float2bfloat16(hpair[0]);
                __nv_bfloat16 h1 = __float2bfloat16(hpair[1]);
                uint32_t hi2 = (uint32_t)__bfloat16_as_ushort(h0) |
                               ((uint32_t)__bfloat16_as_ushort(h1) << 16);
                uint32_t lo2 = pack_bf2(hpair[0] - __bfloat162float(h0),
                                        hpair[1] - __bfloat162float(h1));
                int row = wm * 32 + mt * 16 + half * 8 + lrow;
                int uw  = wn * 4 + q;
                Aw[row * (ASTR / 4) + wbuf * 64 + uw]      = hi2;
                Aw[row * (ASTR / 4) + wbuf * 64 + 32 + uw] = lo2;
            }

        if (t + 1 < T && xpart < 3) {
            char* ap = smem + xrow * ASTR + 512 + wbuf * 32;
            bool ok = (base + xrow < nrows);
            const float* xr = xin + (size_t)(base + xrow) * TD + (t + 1) * D;
#pragma unroll
            for (int d = 0; d < D; ++d) {
                float v = ok ? xr[d] : 0.0f;
                __nv_bfloat16 hi = __float2bfloat16(v);
                if (xpart == 0)      *(__nv_bfloat16*)(ap + 2 * d) = hi;
                else if (xpart == 1) *(__nv_bfloat16*)(ap + 2 * (D + d)) =
                                         __float2bfloat16(v - __bfloat162float(hi));
                else                 *(__nv_bfloat16*)(ap + 2 * (2 * D + d)) = hi;
            }
        }
        BAR_GRP(1 + wm);
    }

    const float scale = MEAN ? (1.0f / T) : 1.0f;
    const uint32_t fb = (uint32_t)(T & 1);
#pragma unroll
    for (int mt = 0; mt < 2; ++mt)
#pragma unroll
        for (int half = 0; half < 2; ++half) {
            int row = wm * 32 + mt * 16 + half * 8 + lrow;
            int grow = base + row;
            if (grow >= nrows) continue;
            int unit0 = wn * 8 + 2 * q;
            float2 v;
            if (MEAN) {
                int ci0 = mt * 4 + half * 2;
                v = make_float2(outv[ci0] * scale, outv[ci0 + 1] * scale);
            } else {
                uint32_t hi2 = Aw[row * (ASTR / 4) + fb * 64 + wn * 4 + q];
                uint32_t lo2 = Aw[row * (ASTR / 4) + fb * 64 + 32 + wn * 4 + q];
                v = make_float2(bf_lo(hi2) + bf_lo(lo2), bf_hi(hi2) + bf_hi(lo2));
            }
            *(float2*)&emb_out[(size_t)grow * 64 + unit0] = v;
            *(float2*)&g_x[(size_t)(xnode_off + grow) * 64 + unit0] = v;
        }
}

__global__ __launch_bounds__(512, 2)
void lstm_unified_kernel(const float* __restrict__ agent_hist,
                         const float* __restrict__ Wih_a,
                         const float* __restrict__ Whh_a,
                         const float* __restrict__ b_a,
                         const float* __restrict__ lane_nodes,
                         const float* __restrict__ Wih_l,
                         const float* __restrict__ Whh_l,
                         const float* __restrict__ b_l,
                         float* __restrict__ out)
{
    extern __shared__ char smem[];
    if (blockIdx.x < AGENT_BLOCKS) {
        lstm_body<20, 5, false>(smem, agent_hist, Wih_a, Whh_a, b_a,
                                out, 0, A_TOT, blockIdx.x * 64);
    } else {
        lstm_body<10, 2, true>(smem, lane_nodes, Wih_l, Whh_l, b_l,
                               out + (size_t)2 * A_TOT * 64, A_TOT, L_TOT,
                               (blockIdx.x - AGENT_BLOCKS) * 64);
    }
}

// ---------------------------------------------------------------------------
// edge decode + CSR build
// ---------------------------------------------------------------------------
__device__ __forceinline__ void edge_decode(
    int e,
    const int* __restrict__ aa_src, const int* __restrict__ aa_dst,
    const float* __restrict__ len_aa,
    const int* __restrict__ al_a, const int* __restrict__ al_l,
    const float* __restrict__ len_al,
    int& src, int& dst, float& len)
{
    if (e < E_AA) {
        src = aa_src[e]; dst = aa_dst[e]; len = len_aa[e];
    } else if (e < E_AA + E_AL) {
        int i = e - E_AA;
        src = al_a[i]; dst = A_TOT + al_l[i]; len = len_al[i];
    } else {
        int i = e - E_AA - E_AL;
        src = A_TOT + al_l[i]; dst = al_a[i]; len = len_al[i];
    }
}

__global__ void init_kernel() {
    int i = blockIdx.x * blockDim.x + threadIdx.x;
    if (i < N_TOT) { g_deg[i] = 1.0f; g_cnt[i] = 0; }
    if (i < 256) g_stats[i] = 0.0f;
}

__global__ void hist_kernel(const int* __restrict__ aa_src, const int* __restrict__ aa_dst,
                            const float* __restrict__ len_aa,
                            const int* __restrict__ al_a, const int* __restrict__ al_l,
                            const float* __restrict__ len_al,
                            const float* __restrict__ w_e, const float* __restrict__ b_e) {
    int e = blockIdx.x * blockDim.x + threadIdx.x;
    if (e >= ETOT) return;
    int src, dst; float len;
    edge_decode(e, aa_src, aa_dst, len_aa, al_a, al_l, len_al, src, dst, len);
    float w = sigmoidf_(fmaf(len, w_e[0], b_e[0]));
    atomicAdd(&g_deg[dst], w);
    atomicAdd(&g_cnt[dst], 1);
}

// ---- parallel 3-phase scan -------------------------------------------------
__global__ __launch_bounds__(256)
void scan1_kernel() {
    __shared__ int sh[256];
    int i = blockIdx.x * 256 + threadIdx.x;
    sh[threadIdx.x] = (i < N_TOT) ? g_cnt[i] : 0;
    __syncthreads();
    for (int off = 128; off > 0; off >>= 1) {
        if (threadIdx.x < off) sh[threadIdx.x] += sh[threadIdx.x + off];
        __syncthreads();
    }
    if (threadIdx.x == 0) g_bsum[blockIdx.x] = sh[0];
}

__global__ __launch_bounds__(512)
void scan2_kernel() {
    __shared__ int sh[512];
    int t = threadIdx.x;
    int v = (t < SCAN_BLOCKS) ? g_bsum[t] : 0;
    sh[t] = v;
    __syncthreads();
    for (int off = 1; off < 512; off <<= 1) {
        int u = (t >= off) ? sh[t - off] : 0;
        __syncthreads();
        sh[t] += u;
        __syncthreads();
    }
    if (t < SCAN_BLOCKS) g_bbase[t] = sh[t] - v;   // exclusive
    if (t == 0) g_rowptr[N_TOT] = ETOT;
}

__global__ __launch_bounds__(256)
void scan3_kernel() {
    __shared__ int sh[256];
    int i = blockIdx.x * 256 + threadIdx.x;
    int t = threadIdx.x;
    int v = (i < N_TOT) ? g_cnt[i] : 0;
    sh[t] = v;
    __syncthreads();
    for (int off = 1; off < 256; off <<= 1) {
        int u = (t >= off) ? sh[t - off] : 0;
        __syncthreads();
        sh[t] += u;
        __syncthreads();
    }
    if (i < N_TOT) {
        int excl = g_bbase[blockIdx.x] + sh[t] - v;
        g_rowptr[i] = excl;
        g_cursor[i] = excl;
        float d = g_deg[i];
        g_dinv[i] = (d > 0.0f) ? rsqrtf(d) : 0.0f;
    }
}

__global__ void scatter_kernel(const int* __restrict__ aa_src, const int* __restrict__ aa_dst,
                               const float* __restrict__ len_aa,
                               const int* __restrict__ al_a, const int* __restrict__ al_l,
                               const float* __restrict__ len_al,
                               const float* __restrict__ w_e, const float* __restrict__ b_e) {
    int e = blockIdx.x * blockDim.x + threadIdx.x;
    if (e >= ETOT) return;
    int src, dst; float len;
    edge_decode(e, aa_src, aa_dst, len_aa, al_a, al_l, len_al, src, dst, len);
    float w = sigmoidf_(fmaf(len, w_e[0], b_e[0]));
    float nrm = g_dinv[src] * w * g_dinv[dst];
    int pos = atomicAdd(&g_cursor[dst], 1);
    g_epack[pos] = make_int2(src, __float_as_int(nrm));
}

// ---------------------------------------------------------------------------
__global__ __launch_bounds__(256)
void lin_kernel(const float* __restrict__ W, int in_sel, int use_bn) {
    __shared__ float Ws[64 * 65];
    __shared__ float xsh[64 * 65];
    const float* in = in_sel ? g_out1 : g_x;

    int tid = threadIdx.x;
    for (int idx = tid; idx < 64 * 64; idx += 256) {
        int k = idx >> 6, j = idx & 63;
        Ws[k * 65 + j] = W[idx];
    }
    int base = blockIdx.x * 64;
    for (int idx = tid; idx < 64 * 64; idx += 256) {
        int r = idx >> 6, k = idx & 63;
        int row = base + r;
        float v = (row < N_TOT) ? in[(size_t)row * 64 + k] : 0.0f;
        if (use_bn) v = fmaxf(fmaf(v, g_stats[128 + k], g_stats[192 + k]), 0.0f);
        xsh[r * 65 + k] = v;
    }
    __syncthreads();

    int j = tid & 63, rl = tid >> 6;
    for (int rr = rl; rr < 64; rr += 4) {
        float a = 0.0f;
#pragma unroll
        for (int k = 0; k < 64; ++k) a = fmaf(xsh[rr * 65 + k], Ws[k * 65 + j], a);
        int row = base + rr;
        if (row < N_TOT) g_h[(size_t)row * 64 + j] = a;
    }
}

// ---------------------------------------------------------------------------
__global__ __launch_bounds__(256)
void agg_csr_kernel(const float* __restrict__ bvec, float* __restrict__ dout, int map) {
    int node = blockIdx.x * 8 + (threadIdx.x >> 5);
    if (node >= N_TOT) return;
    int lane = threadIdx.x & 31;

    int beg = g_rowptr[node], end = g_rowptr[node + 1];

    float ax = 0.0f, ay = 0.0f;
    int e = beg;
    for (; e + 3 < end; e += 4) {
        int2 p0 = g_epack[e];
        int2 p1 = g_epack[e + 1];
        int2 p2 = g_epack[e + 2];
        int2 p3 = g_epack[e + 3];
        float2 v0 = *(const float2*)&g_h[(size_t)p0.x * 64 + 2 * lane];
        float2 v1 = *(const float2*)&g_h[(size_t)p1.x * 64 + 2 * lane];
        float2 v2 = *(const float2*)&g_h[(size_t)p2.x * 64 + 2 * lane];
        float2 v3 = *(const float2*)&g_h[(size_t)p3.x * 64 + 2 * lane];
        float n0 = __int_as_float(p0.y), n1 = __int_as_float(p1.y);
        float n2 = __int_as_float(p2.y), n3 = __int_as_float(p3.y);
        ax = fmaf(v0.x, n0, ax); ay = fmaf(v0.y, n0, ay);
        ax = fmaf(v1.x, n1, ax); ay = fmaf(v1.y, n1, ay);
        ax = fmaf(v2.x, n2, ax); ay = fmaf(v2.y, n2, ay);
        ax = fmaf(v3.x, n3, ax); ay = fmaf(v3.y, n3, ay);
    }
    for (; e < end; ++e) {
        int2 p0 = g_epack[e];
        float2 v0 = *(const float2*)&g_h[(size_t)p0.x * 64 + 2 * lane];
        float n0 = __int_as_float(p0.y);
        ax = fmaf(v0.x, n0, ax); ay = fmaf(v0.y, n0, ay);
    }

    float di = g_dinv[node];
    float dd = di * di;
    float2 hv = *(const float2*)&g_h[(size_t)node * 64 + 2 * lane];
    float2 bv = *(const float2*)&bvec[2 * lane];
    float2 res;
    res.x = fmaf(hv.x, dd, ax) + bv.x;
    res.y = fmaf(hv.y, dd, ay) + bv.y;

    float* op;
    if (map) {
        size_t off = (node < A_TOT) ? ((size_t)(A_TOT + node) * 64)
                                    : ((size_t)(A_TOT + L_TOT + node) * 64);
        op = dout + off;
    } else {
        op = g_out1 + (size_t)node * 64;
    }
    *(float2*)(op + 2 * lane) = res;
}

// ---------------------------------------------------------------------------
__global__ __launch_bounds__(256)
void bn_stats_kernel() {
    __shared__ float sh[512];
    int tid = threadIdx.x;
    int j = tid & 63;
    float s = 0.0f, s2 = 0.0f;
    for (int row = blockIdx.x * 4 + (tid >> 6); row < N_TOT; row += gridDim.x * 4) {
        float v = g_out1[(size_t)row * 64 + j];
        s += v; s2 += v * v;
    }
    sh[tid] = s; sh[256 + tid] = s2;
    __syncthreads();
    if (tid < 64) {
        float t = sh[tid] + sh[tid + 64] + sh[tid + 128] + sh[tid + 192];
        atomicAdd(&g_stats[tid], t);
    } else if (tid < 128) {
        int jj = tid - 64;
        float t = sh[256 + jj] + sh[256 + jj + 64] + sh[256 + jj + 128] + sh[256 + jj + 192];
        atomicAdd(&g_stats[64 + jj], t);
    }
}

__global__ void bn_final_kernel(const float* __restrict__ gamma, const float* __restrict__ beta) {
    int j = threadIdx.x;
    if (j >= 64) return;
    float mean = g_stats[j] * (1.0f / N_TOT);
    float var  = g_stats[64 + j] * (1.0f / N_TOT) - mean * mean;
    float rs   = rsqrtf(var + BN_EPS);
    float sc   = rs * gamma[j];
    g_stats[128 + j] = sc;
    g_stats[192 + j] = beta[j] - mean * sc;
}

// ---------------------------------------------------------------------------
extern "C" void kernel_launch(void* const* d_in, const int* in_sizes, int n_in,
                              void* d_out, int out_size) {
    const float* agent_hist = (const float*)d_in[0];
    const float* lane_nodes = (const float*)d_in[1];
    const int*   eaa        = (const int*)d_in[2];
    const float* len_aa     = (const float*)d_in[3];
    const int*   eal        = (const int*)d_in[4];
    const float* len_al     = (const float*)d_in[5];
    const float* Wih_a      = (const float*)d_in[6];
    const float* Whh_a      = (const float*)d_in[7];
    const float* b_a        = (const float*)d_in[8];
    const float* Wih_l      = (const float*)d_in[9];
    const float* Whh_l      = (const float*)d_in[10];
    const float* b_l        = (const float*)d_in[11];
    const float* w_e        = (const float*)d_in[12];
    const float* b_e        = (const float*)d_in[13];
    const float* W1         = (const float*)d_in[14];
    const float* b1         = (const float*)d_in[15];
    const float* gamma1     = (const float*)d_in[16];
    const float* beta1      = (const float*)d_in[17];
    const float* W2         = (const float*)d_in[18];
    const float* b2         = (const float*)d_in[19];
    float* out = (float*)d_out;

    const int* aa_src = eaa;
    const int* aa_dst = eaa + E_AA;
    const int* al_a   = eal;
    const int* al_l   = eal + E_AL;

    cudaFuncSetAttribute((const void*)lstm_unified_kernel,
                         cudaFuncAttributeMaxDynamicSharedMemorySize, LSTM_SMEM);

    // fork a side branch for the CSR build so it overlaps the LSTM
    cudaStream_t s2;
    cudaStreamCreateWithFlags(&s2, cudaStreamNonBlocking);
    cudaEvent_t evFork, evJoin;
    cudaEventCreateWithFlags(&evFork, cudaEventDisableTiming);
    cudaEventCreateWithFlags(&evJoin, cudaEventDisableTiming);

    cudaEventRecord(evFork, 0);
    cudaStreamWaitEvent(s2, evFork, 0);

    // side branch: CSR build (independent of LSTM)
    init_kernel<<<(N_TOT + 255) / 256, 256, 0, s2>>>();
    hist_kernel<<<(ETOT + 255) / 256, 256, 0, s2>>>(aa_src, aa_dst, len_aa,
                                                    al_a, al_l, len_al, w_e, b_e);
    scan1_kernel<<<SCAN_BLOCKS, 256, 0, s2>>>();
    scan2_kernel<<<1, 512, 0, s2>>>();
    scan3_kernel<<<SCAN_BLOCKS, 256, 0, s2>>>();
    scatter_kernel<<<(ETOT + 255) / 256, 256, 0, s2>>>(aa_src, aa_dst, len_aa,
                                                       al_a, al_l, len_al, w_e, b_e);
    cudaEventRecord(evJoin, s2);

    // main branch: LSTM
    lstm_unified_kernel<<<AGENT_BLOCKS + LANE_BLOCKS, 512, LSTM_SMEM>>>(
        agent_hist, Wih_a, Whh_a, b_a, lane_nodes, Wih_l, Whh_l, b_l, out);

    // join: conv chain needs both branches
    cudaStreamWaitEvent(0, evJoin, 0);

    lin_kernel<<<(N_TOT + 63) / 64, 256>>>(W1, 0, 0);
    agg_csr_kernel<<<(N_TOT + 7) / 8, 256>>>(b1, out, 0);

    bn_stats_kernel<<<512, 256>>>();
    bn_final_kernel<<<1, 64>>>(gamma1, beta1);

    lin_kernel<<<(N_TOT + 63) / 64, 256>>>(W2, 1, 1);
    agg_csr_kernel<<<(N_TOT + 7) / 8, 256>>>(b2, out, 1);

    cudaEventDestroy(evFork);
    cudaEventDestroy(evJoin);
    cudaStreamDestroy(s2);
}